// round 1
// baseline (speedup 1.0000x reference)
#include <cuda_runtime.h>
#include <math_constants.h>

// ---------------------------------------------------------------------------
// Problem constants
// ---------------------------------------------------------------------------
#define B_ 8
#define S_ 2048
#define D_ 1024

// Scratch (device globals: allocation-free rule)
__device__ float g_Q[B_ * S_ * D_];     // 64 MB
__device__ float g_K[B_ * S_ * D_];     // 64 MB
__device__ float g_V[B_ * S_ * D_];     // 64 MB
__device__ float g_S[B_ * S_ * S_];     // 128 MB (scores, then probs in-place)

// ---------------------------------------------------------------------------
// Tiled SGEMM: C[m,n] = alpha * sum_k A[m,k] * B'[k,n] (+ bias[n])
//   TRANS_B = true : B stored row-major [N,K]  (B'[k,n] = B[n*ldk + k])  -> NT
//   TRANS_B = false: B stored row-major [K,N]  (B'[k,n] = B[k*N + n])    -> NN
// 128x128 tile, BK=8, 256 threads, 8x8 microtile per thread.
// All dims are multiples of the tile sizes here; no bounds checks.
// ---------------------------------------------------------------------------
#define BM 128
#define BN 128
#define BK 8
#define TM 8
#define TN 8

template <bool TRANS_B, bool HAS_BIAS>
__global__ __launch_bounds__(256, 2)
void gemm_kernel(const float* __restrict__ A,
                 const float* __restrict__ Bm,
                 const float* __restrict__ bias,
                 float* __restrict__ C,
                 int M, int N, int K, float alpha,
                 long long strideA, long long strideB, long long strideC)
{
    const int bz = blockIdx.z;
    A  += (long long)bz * strideA;
    Bm += (long long)bz * strideB;
    C  += (long long)bz * strideC;

    __shared__ float As[BK][BM + 4];
    __shared__ float Bs[BK][BN + 4];

    const int tid = threadIdx.x;              // 0..255
    const int bm = blockIdx.y * BM;
    const int bn = blockIdx.x * BN;

    // A loader: row-major [M,K]; 128 rows x 8 k per tile; 2 threads/row, float4
    const int a_row = tid >> 1;               // 0..127
    const int a_k   = (tid & 1) * 4;          // 0 or 4
    // NN B loader: [K,N]; 8 rows x 128 cols; float4 along n
    const int b_k = tid >> 5;                 // 0..7
    const int b_n = (tid & 31) * 4;           // 0..124

    const int ty = tid >> 4;                  // 0..15
    const int tx = tid & 15;                  // 0..15

    float acc[TM][TN];
#pragma unroll
    for (int i = 0; i < TM; i++)
#pragma unroll
        for (int j = 0; j < TN; j++) acc[i][j] = 0.f;

    for (int k0 = 0; k0 < K; k0 += BK) {
        // --- load A tile (transpose into smem) ---
        {
            float4 av = *(const float4*)&A[(long long)(bm + a_row) * K + k0 + a_k];
            As[a_k + 0][a_row] = av.x;
            As[a_k + 1][a_row] = av.y;
            As[a_k + 2][a_row] = av.z;
            As[a_k + 3][a_row] = av.w;
        }
        // --- load B tile ---
        if (TRANS_B) {
            float4 bv = *(const float4*)&Bm[(long long)(bn + a_row) * K + k0 + a_k];
            Bs[a_k + 0][a_row] = bv.x;
            Bs[a_k + 1][a_row] = bv.y;
            Bs[a_k + 2][a_row] = bv.z;
            Bs[a_k + 3][a_row] = bv.w;
        } else {
            float4 bv = *(const float4*)&Bm[(long long)(k0 + b_k) * N + bn + b_n];
            *(float4*)&Bs[b_k][b_n] = bv;
        }
        __syncthreads();

#pragma unroll
        for (int kk = 0; kk < BK; kk++) {
            float4 a0 = *(const float4*)&As[kk][ty * TM];
            float4 a1 = *(const float4*)&As[kk][ty * TM + 4];
            float4 b0 = *(const float4*)&Bs[kk][tx * TN];
            float4 b1 = *(const float4*)&Bs[kk][tx * TN + 4];
            float ra[TM] = {a0.x, a0.y, a0.z, a0.w, a1.x, a1.y, a1.z, a1.w};
            float rb[TN] = {b0.x, b0.y, b0.z, b0.w, b1.x, b1.y, b1.z, b1.w};
#pragma unroll
            for (int i = 0; i < TM; i++)
#pragma unroll
                for (int j = 0; j < TN; j++)
                    acc[i][j] = fmaf(ra[i], rb[j], acc[i][j]);
        }
        __syncthreads();
    }

    // --- epilogue ---
    float rbias[TN];
#pragma unroll
    for (int j = 0; j < TN; j++)
        rbias[j] = HAS_BIAS ? bias[bn + tx * TN + j] : 0.f;

#pragma unroll
    for (int i = 0; i < TM; i++) {
        long long r = (long long)(bm + ty * TM + i) * N + bn + tx * TN;
        float4 o0, o1;
        o0.x = acc[i][0] * alpha + rbias[0];
        o0.y = acc[i][1] * alpha + rbias[1];
        o0.z = acc[i][2] * alpha + rbias[2];
        o0.w = acc[i][3] * alpha + rbias[3];
        o1.x = acc[i][4] * alpha + rbias[4];
        o1.y = acc[i][5] * alpha + rbias[5];
        o1.z = acc[i][6] * alpha + rbias[6];
        o1.w = acc[i][7] * alpha + rbias[7];
        *(float4*)&C[r]     = o0;
        *(float4*)&C[r + 4] = o1;
    }
}

// ---------------------------------------------------------------------------
// Masked softmax over rows of g_S (in-place). One block per (b, q) row.
// mask[b, k] == 0 -> weight 0. 256 threads, 8 cols/thread (S=2048).
// ---------------------------------------------------------------------------
__global__ __launch_bounds__(256)
void softmax_kernel(float* __restrict__ scores, const int* __restrict__ mask)
{
    const int row = blockIdx.x;               // 0..B*S-1
    const int b   = row / S_;
    float* p = scores + (long long)row * S_;
    const int* mrow = mask + (long long)b * S_;

    const int tid = threadIdx.x;
    const int c0 = tid * 8;

    float4 v0 = *(const float4*)&p[c0];
    float4 v1 = *(const float4*)&p[c0 + 4];
    int4 m0 = *(const int4*)&mrow[c0];
    int4 m1 = *(const int4*)&mrow[c0 + 4];

    float v[8]   = {v0.x, v0.y, v0.z, v0.w, v1.x, v1.y, v1.z, v1.w};
    int   mk[8]  = {m0.x, m0.y, m0.z, m0.w, m1.x, m1.y, m1.z, m1.w};

    // --- max over unmasked ---
    float mx = -CUDART_INF_F;
#pragma unroll
    for (int i = 0; i < 8; i++)
        if (mk[i]) mx = fmaxf(mx, v[i]);
#pragma unroll
    for (int o = 16; o > 0; o >>= 1)
        mx = fmaxf(mx, __shfl_xor_sync(0xFFFFFFFFu, mx, o));

    __shared__ float sred[8];
    if ((tid & 31) == 0) sred[tid >> 5] = mx;
    __syncthreads();
    mx = sred[0];
#pragma unroll
    for (int w = 1; w < 8; w++) mx = fmaxf(mx, sred[w]);
    __syncthreads();

    const bool any_valid = (mx > -CUDART_INF_F);
    const float mxs = any_valid ? mx : 0.f;

    // --- exp & sum ---
    float sum = 0.f;
#pragma unroll
    for (int i = 0; i < 8; i++) {
        float e = mk[i] ? __expf(v[i] - mxs) : 0.f;
        v[i] = e;
        sum += e;
    }
#pragma unroll
    for (int o = 16; o > 0; o >>= 1)
        sum += __shfl_xor_sync(0xFFFFFFFFu, sum, o);
    if ((tid & 31) == 0) sred[tid >> 5] = sum;
    __syncthreads();
    sum = 0.f;
#pragma unroll
    for (int w = 0; w < 8; w++) sum += sred[w];

    const float inv = (sum > 0.f) ? (1.f / sum) : 0.f;

    float4 o0, o1;
    o0.x = v[0] * inv; o0.y = v[1] * inv; o0.z = v[2] * inv; o0.w = v[3] * inv;
    o1.x = v[4] * inv; o1.y = v[5] * inv; o1.z = v[6] * inv; o1.w = v[7] * inv;
    *(float4*)&p[c0]     = o0;
    *(float4*)&p[c0 + 4] = o1;
}

// ---------------------------------------------------------------------------
// Launch
// ---------------------------------------------------------------------------
extern "C" void kernel_launch(void* const* d_in, const int* in_sizes, int n_in,
                              void* d_out, int out_size)
{
    const float* query = (const float*)d_in[0];
    const float* key   = (const float*)d_in[1];
    const float* value = (const float*)d_in[2];
    const int*   mask  = (const int*)  d_in[3];
    const float* Wq    = (const float*)d_in[4];
    const float* bq    = (const float*)d_in[5];
    const float* Wk    = (const float*)d_in[6];
    const float* bk    = (const float*)d_in[7];
    const float* Wv    = (const float*)d_in[8];
    const float* bv    = (const float*)d_in[9];
    float* out = (float*)d_out;

    float *Q, *K, *V, *Sc;
    cudaGetSymbolAddress((void**)&Q,  g_Q);
    cudaGetSymbolAddress((void**)&K,  g_K);
    cudaGetSymbolAddress((void**)&V,  g_V);
    cudaGetSymbolAddress((void**)&Sc, g_S);

    const int M = B_ * S_;                      // 16384
    const float inv_sqrt_d = 1.0f / 32.0f;      // 1/sqrt(1024)

    dim3 blk(256);

    // Projections: [16384,1024] = X[16384,1024] @ W^T[1024,1024] + b  (NT)
    dim3 gproj(D_ / BN, M / BM, 1);
    gemm_kernel<true, true><<<gproj, blk>>>(query, Wq, bq, Q, M, D_, D_, 1.0f, 0, 0, 0);
    gemm_kernel<true, true><<<gproj, blk>>>(key,   Wk, bk, K, M, D_, D_, 1.0f, 0, 0, 0);
    gemm_kernel<true, true><<<gproj, blk>>>(value, Wv, bv, V, M, D_, D_, 1.0f, 0, 0, 0);

    // Scores: per-batch [2048,2048] = Q[2048,1024] @ K^T  (NT), alpha = 1/sqrt(D)
    dim3 gsc(S_ / BN, S_ / BM, B_);
    gemm_kernel<true, false><<<gsc, blk>>>(Q, K, nullptr, Sc, S_, S_, D_, inv_sqrt_d,
                                           (long long)S_ * D_, (long long)S_ * D_,
                                           (long long)S_ * S_);

    // Masked softmax (in-place on Sc)
    softmax_kernel<<<B_ * S_, blk>>>(Sc, mask);

    // Out: per-batch [2048,1024] = P[2048,2048] @ V[2048,1024]  (NN)
    dim3 gpv(D_ / BN, S_ / BM, B_);
    gemm_kernel<false, false><<<gpv, blk>>>(Sc, V, nullptr, out, S_, D_, S_, 1.0f,
                                            (long long)S_ * S_, (long long)S_ * D_,
                                            (long long)S_ * D_);
}

// round 3
// speedup vs baseline: 1.5664x; 1.5664x over previous
#include <cuda_runtime.h>
#include <cuda_bf16.h>
#include <math_constants.h>
#include <cstdint>

// ---------------------------------------------------------------------------
// Problem constants
// ---------------------------------------------------------------------------
#define B_ 8
#define S_ 2048
#define D_ 1024

typedef __nv_bfloat16 bf16;

// ---------------------------------------------------------------------------
// Scratch (device globals; allocation-free rule)
// ---------------------------------------------------------------------------
__device__ bf16 gXqH[B_*S_*D_], gXqL[B_*S_*D_];
__device__ bf16 gXkH[B_*S_*D_], gXkL[B_*S_*D_];
__device__ bf16 gXvH[B_*S_*D_], gXvL[B_*S_*D_];
__device__ bf16 gWqH[D_*D_], gWqL[D_*D_];
__device__ bf16 gWkH[D_*D_], gWkL[D_*D_];
__device__ bf16 gWvH[D_*D_], gWvL[D_*D_];
__device__ bf16 gQH[B_*S_*D_], gQL[B_*S_*D_];
__device__ bf16 gKH[B_*S_*D_], gKL[B_*S_*D_];
__device__ bf16 gVH[B_*S_*D_], gVL[B_*S_*D_];
__device__ bf16 gVtH[B_*S_*D_], gVtL[B_*S_*D_];
__device__ float gScores[B_*S_*S_];
__device__ bf16 gPH[(long long)B_*S_*S_], gPL[(long long)B_*S_*S_];

// ---------------------------------------------------------------------------
// PTX helpers (sm_80-baseline only: cp.async, ldmatrix, mma.sync)
// ---------------------------------------------------------------------------
__device__ __forceinline__ uint32_t smem_u32(const void* p) {
    uint32_t a;
    asm("{ .reg .u64 t; cvta.to.shared.u64 t, %1; cvt.u32.u64 %0, t; }" : "=r"(a) : "l"(p));
    return a;
}
__device__ __forceinline__ void cp16(uint32_t dst, const void* src) {
    asm volatile("cp.async.cg.shared.global [%0], [%1], 16;"
                 :: "r"(dst), "l"(__cvta_generic_to_global(src)) : "memory");
}
#define CP_COMMIT() asm volatile("cp.async.commit_group;" ::: "memory")
#define CP_WAIT(n)  asm volatile("cp.async.wait_group %0;" :: "n"(n) : "memory")

__device__ __forceinline__ void ldm_x4(uint32_t* r, uint32_t addr) {
    asm volatile("ldmatrix.sync.aligned.m8n8.x4.shared.b16 {%0,%1,%2,%3}, [%4];"
                 : "=r"(r[0]), "=r"(r[1]), "=r"(r[2]), "=r"(r[3]) : "r"(addr));
}
__device__ __forceinline__ void mma_bf16(float* d, const uint32_t* a, const uint32_t* b) {
    asm volatile("mma.sync.aligned.m16n8k16.row.col.f32.bf16.bf16.f32 "
                 "{%0,%1,%2,%3}, {%4,%5,%6,%7}, {%8,%9}, {%0,%1,%2,%3};"
                 : "+f"(d[0]), "+f"(d[1]), "+f"(d[2]), "+f"(d[3])
                 : "r"(a[0]), "r"(a[1]), "r"(a[2]), "r"(a[3]), "r"(b[0]), "r"(b[1]));
}

// ---------------------------------------------------------------------------
// GEMM: C[M,N] = sum_k A[M,K] * B[N,K]^T, split-bf16 3-pass, mma.sync
// Tile 128x128, BK=32, 8 warps (2m x 4n, each 64x32), 4-stage cp.async.
// SMEM rows: 32 bf16 = 64B data at 80B stride (conflict-free ldmatrix).
// EPI==0: fp32 store of acc. EPI==1: split-bf16 store of (acc+bias)*scale.
// ---------------------------------------------------------------------------
#define BK_ 32
#define ROWB 80
#define MATB (128 * ROWB)          // 10240
#define STAGEB (4 * MATB)          // 40960 (Ah, Al, Bh, Bl)
#define NSTAGE 4
#define SMEM_DYN (NSTAGE * STAGEB) // 163840

__device__ __forceinline__ void load_stage(uint32_t sbase, int slot, int tid,
                                           const bf16* Ah, const bf16* Al,
                                           const bf16* Bh, const bf16* Bl,
                                           int bm, int bn, int K, int k0)
{
    uint32_t sb = sbase + (uint32_t)slot * STAGEB;
#pragma unroll
    for (int t = 0; t < 2; t++) {
        int u = tid + 256 * t;              // 0..511
        int row = u >> 2;                   // 0..127
        int c = (u & 3) * 16;               // byte offset within 64B row
        uint32_t so = (uint32_t)(row * ROWB + c);
        size_t gA = (size_t)(bm + row) * K + k0 + (c >> 1);
        size_t gB = (size_t)(bn + row) * K + k0 + (c >> 1);
        cp16(sb + so,            Ah + gA);
        cp16(sb + MATB + so,     Al + gA);
        cp16(sb + 2 * MATB + so, Bh + gB);
        cp16(sb + 3 * MATB + so, Bl + gB);
    }
    CP_COMMIT();
}

template <int EPI>
__global__ __launch_bounds__(256, 1)
void mma_gemm(const bf16* __restrict__ Ah, const bf16* __restrict__ Al,
              const bf16* __restrict__ Bh, const bf16* __restrict__ Bl,
              const float* __restrict__ bias, float scale,
              float* __restrict__ Cf, bf16* __restrict__ Ch, bf16* __restrict__ Cl,
              int M, int N, int K,
              long long sA, long long sB, long long sC)
{
    extern __shared__ char smem[];
    const int tid  = threadIdx.x;
    const int wid  = tid >> 5;
    const int lane = tid & 31;

    const int bz = blockIdx.z;
    Ah += (long long)bz * sA;  Al += (long long)bz * sA;
    Bh += (long long)bz * sB;  Bl += (long long)bz * sB;

    const int bm = blockIdx.y * 128;
    const int bn = blockIdx.x * 128;
    const int wm = (wid >> 2) * 64;         // warp m offset in tile
    const int wn = (wid & 3) * 32;          // warp n offset in tile

    const uint32_t sbase = smem_u32(smem);

    float acc[4][4][4];
#pragma unroll
    for (int i = 0; i < 4; i++)
#pragma unroll
        for (int j = 0; j < 4; j++)
#pragma unroll
            for (int q = 0; q < 4; q++) acc[i][j][q] = 0.f;

    const int NITER = K / BK_;              // >= 32 always here

    load_stage(sbase, 0, tid, Ah, Al, Bh, Bl, bm, bn, K, 0);
    load_stage(sbase, 1, tid, Ah, Al, Bh, Bl, bm, bn, K, BK_);
    load_stage(sbase, 2, tid, Ah, Al, Bh, Bl, bm, bn, K, 2 * BK_);

    // ldmatrix lane addressing (within the current stage):
    // A x4: row = lane&15 (within 16-row frag), k half = lane>>4 (0/8 elems)
    const int a_row = lane & 15;
    const int a_k16 = (lane >> 4) * 16;     // bytes (8 bf16)
    // B x4: covers two n8 frags; rows (lane&7) + 8*(lane>>4), k half (lane>>3)&1
    const int b_row = (lane & 7) + ((lane >> 4) << 3);
    const int b_k16 = ((lane >> 3) & 1) * 16;

    for (int i = 0; i < NITER; i++) {
        if (i < NITER - 2)      CP_WAIT(2);
        else if (i == NITER - 2) CP_WAIT(1);
        else                     CP_WAIT(0);
        __syncthreads();

        if (i + 3 < NITER)
            load_stage(sbase, (i + 3) & 3, tid, Ah, Al, Bh, Bl, bm, bn, K, (i + 3) * BK_);

        uint32_t st = sbase + (uint32_t)(i & 3) * STAGEB;
#pragma unroll
        for (int ks = 0; ks < 2; ks++) {
            const int kb = ks * 32;         // byte offset of this k16 step (16 bf16)
            uint32_t ah[4][4], al[4][4];
#pragma unroll
            for (int mf = 0; mf < 4; mf++) {
                uint32_t ra = st + (uint32_t)((wm + mf * 16 + a_row) * ROWB + kb + a_k16);
                ldm_x4(ah[mf], ra);
                ldm_x4(al[mf], ra + MATB);
            }
            uint32_t bh[4][2], bl[4][2];
#pragma unroll
            for (int np = 0; np < 2; np++) {  // each x4 covers 2 n-frags
                uint32_t rb = st + 2 * MATB +
                              (uint32_t)((wn + np * 16 + b_row) * ROWB + kb + b_k16);
                uint32_t th[4], tl[4];
                ldm_x4(th, rb);
                ldm_x4(tl, rb + MATB);
                bh[np*2][0]   = th[0]; bh[np*2][1]   = th[1];
                bh[np*2+1][0] = th[2]; bh[np*2+1][1] = th[3];
                bl[np*2][0]   = tl[0]; bl[np*2][1]   = tl[1];
                bl[np*2+1][0] = tl[2]; bl[np*2+1][1] = tl[3];
            }
#pragma unroll
            for (int mf = 0; mf < 4; mf++)
#pragma unroll
                for (int nf = 0; nf < 4; nf++) {
                    mma_bf16(acc[mf][nf], ah[mf], bh[nf]);
                    mma_bf16(acc[mf][nf], ah[mf], bl[nf]);
                    mma_bf16(acc[mf][nf], al[mf], bh[nf]);
                }
        }
    }

    // ---- epilogue (register -> global, no smem) ----
    const int rr = lane >> 2;               // 0..7
    const int cc = (lane & 3) * 2;          // 0,2,4,6
#pragma unroll
    for (int mf = 0; mf < 4; mf++) {
#pragma unroll
        for (int nf = 0; nf < 4; nf++) {
            const int row = bm + wm + mf * 16 + rr;
            const int col = bn + wn + nf * 8 + cc;
            float* a4 = acc[mf][nf];
            if (EPI == 0) {
                float* dst = Cf + (long long)bz * sC;
                float2 v0 = make_float2(a4[0], a4[1]);
                float2 v1 = make_float2(a4[2], a4[3]);
                *(float2*)&dst[(size_t)row * N + col]       = v0;
                *(float2*)&dst[(size_t)(row + 8) * N + col] = v1;
            } else {
                float b0 = bias[col], b1 = bias[col + 1];
                float v0 = (a4[0] + b0) * scale;
                float v1 = (a4[1] + b1) * scale;
                float v2 = (a4[2] + b0) * scale;
                float v3 = (a4[3] + b1) * scale;
                bf16 h0 = __float2bfloat16_rn(v0);
                bf16 h1 = __float2bfloat16_rn(v1);
                bf16 h2 = __float2bfloat16_rn(v2);
                bf16 h3 = __float2bfloat16_rn(v3);
                bf16 l0 = __float2bfloat16_rn(v0 - __bfloat162float(h0));
                bf16 l1 = __float2bfloat16_rn(v1 - __bfloat162float(h1));
                bf16 l2 = __float2bfloat16_rn(v2 - __bfloat162float(h2));
                bf16 l3 = __float2bfloat16_rn(v3 - __bfloat162float(h3));
                __nv_bfloat162 ph0; ph0.x = h0; ph0.y = h1;
                __nv_bfloat162 ph1; ph1.x = h2; ph1.y = h3;
                __nv_bfloat162 pl0; pl0.x = l0; pl0.y = l1;
                __nv_bfloat162 pl1; pl1.x = l2; pl1.y = l3;
                *(__nv_bfloat162*)&Ch[(size_t)row * N + col]       = ph0;
                *(__nv_bfloat162*)&Ch[(size_t)(row + 8) * N + col] = ph1;
                *(__nv_bfloat162*)&Cl[(size_t)row * N + col]       = pl0;
                *(__nv_bfloat162*)&Cl[(size_t)(row + 8) * N + col] = pl1;
            }
        }
    }
}

// ---------------------------------------------------------------------------
// fp32 -> split bf16 (hi, lo)
// ---------------------------------------------------------------------------
__global__ __launch_bounds__(256)
void split_kernel(const float4* __restrict__ src, uint2* __restrict__ hi,
                  uint2* __restrict__ lo)
{
    int i = blockIdx.x * 256 + threadIdx.x;
    float4 v = src[i];
    __align__(8) bf16 h[4], l[4];
    float f[4] = {v.x, v.y, v.z, v.w};
#pragma unroll
    for (int q = 0; q < 4; q++) {
        h[q] = __float2bfloat16_rn(f[q]);
        l[q] = __float2bfloat16_rn(f[q] - __bfloat162float(h[q]));
    }
    hi[i] = *(uint2*)h;
    lo[i] = *(uint2*)l;
}

// ---------------------------------------------------------------------------
// per-batch transpose of split V: [B][S][D] -> [B][D][S]
// ---------------------------------------------------------------------------
__global__ __launch_bounds__(256)
void transpose2_kernel(const bf16* __restrict__ srcH, const bf16* __restrict__ srcL,
                       bf16* __restrict__ dstH, bf16* __restrict__ dstL)
{
    __shared__ bf16 tH[32][33];
    __shared__ bf16 tL[32][33];
    const int b = blockIdx.z;
    const int x0 = blockIdx.x * 32;   // D dim
    const int y0 = blockIdx.y * 32;   // S dim
    const int tx = threadIdx.x & 31;
    const int ty = threadIdx.x >> 5;  // 0..7
    const bf16* sH = srcH + (size_t)b * S_ * D_;
    const bf16* sL = srcL + (size_t)b * S_ * D_;
    bf16* dH = dstH + (size_t)b * S_ * D_;
    bf16* dL = dstL + (size_t)b * S_ * D_;
#pragma unroll
    for (int j = 0; j < 4; j++) {
        int r = ty + j * 8;
        tH[r][tx] = sH[(size_t)(y0 + r) * D_ + x0 + tx];
        tL[r][tx] = sL[(size_t)(y0 + r) * D_ + x0 + tx];
    }
    __syncthreads();
#pragma unroll
    for (int j = 0; j < 4; j++) {
        int r = ty + j * 8;
        dH[(size_t)(x0 + r) * S_ + y0 + tx] = tH[tx][r];
        dL[(size_t)(x0 + r) * S_ + y0 + tx] = tL[tx][r];
    }
}

// ---------------------------------------------------------------------------
// Masked softmax: fp32 scores row -> split-bf16 probability row
// ---------------------------------------------------------------------------
__global__ __launch_bounds__(256)
void softmax_kernel(const float* __restrict__ scores, const int* __restrict__ mask,
                    bf16* __restrict__ Ph, bf16* __restrict__ Pl)
{
    const int row = blockIdx.x;               // 0..B*S-1
    const int b   = row / S_;
    const float* p = scores + (long long)row * S_;
    const int* mrow = mask + (long long)b * S_;

    const int tid = threadIdx.x;
    const int c0 = tid * 8;

    float4 v0 = *(const float4*)&p[c0];
    float4 v1 = *(const float4*)&p[c0 + 4];
    int4 m0 = *(const int4*)&mrow[c0];
    int4 m1 = *(const int4*)&mrow[c0 + 4];

    float v[8]  = {v0.x, v0.y, v0.z, v0.w, v1.x, v1.y, v1.z, v1.w};
    int   mk[8] = {m0.x, m0.y, m0.z, m0.w, m1.x, m1.y, m1.z, m1.w};

    float mx = -CUDART_INF_F;
#pragma unroll
    for (int i = 0; i < 8; i++)
        if (mk[i]) mx = fmaxf(mx, v[i]);
#pragma unroll
    for (int o = 16; o > 0; o >>= 1)
        mx = fmaxf(mx, __shfl_xor_sync(0xFFFFFFFFu, mx, o));

    __shared__ float sred[8];
    if ((tid & 31) == 0) sred[tid >> 5] = mx;
    __syncthreads();
    mx = sred[0];
#pragma unroll
    for (int w = 1; w < 8; w++) mx = fmaxf(mx, sred[w]);
    __syncthreads();

    const float mxs = (mx > -CUDART_INF_F) ? mx : 0.f;

    float sum = 0.f;
#pragma unroll
    for (int i = 0; i < 8; i++) {
        float e = mk[i] ? __expf(v[i] - mxs) : 0.f;
        v[i] = e;
        sum += e;
    }
#pragma unroll
    for (int o = 16; o > 0; o >>= 1)
        sum += __shfl_xor_sync(0xFFFFFFFFu, sum, o);
    if ((tid & 31) == 0) sred[tid >> 5] = sum;
    __syncthreads();
    sum = 0.f;
#pragma unroll
    for (int w = 0; w < 8; w++) sum += sred[w];

    const float inv = (sum > 0.f) ? (1.f / sum) : 0.f;

    __align__(16) bf16 hh[8], ll[8];
#pragma unroll
    for (int i = 0; i < 8; i++) {
        float pv = v[i] * inv;
        hh[i] = __float2bfloat16_rn(pv);
        ll[i] = __float2bfloat16_rn(pv - __bfloat162float(hh[i]));
    }
    *(uint4*)&Ph[(long long)row * S_ + c0] = *(uint4*)hh;
    *(uint4*)&Pl[(long long)row * S_ + c0] = *(uint4*)ll;
}

// ---------------------------------------------------------------------------
// Launch
// ---------------------------------------------------------------------------
extern "C" void kernel_launch(void* const* d_in, const int* in_sizes, int n_in,
                              void* d_out, int out_size)
{
    const float* query = (const float*)d_in[0];
    const float* key   = (const float*)d_in[1];
    const float* value = (const float*)d_in[2];
    const int*   mask  = (const int*)  d_in[3];
    const float* Wq    = (const float*)d_in[4];
    const float* bq    = (const float*)d_in[5];
    const float* Wk    = (const float*)d_in[6];
    const float* bk    = (const float*)d_in[7];
    const float* Wv    = (const float*)d_in[8];
    const float* bv    = (const float*)d_in[9];
    float* out = (float*)d_out;

    bf16 *XqH, *XqL, *XkH, *XkL, *XvH, *XvL;
    bf16 *WqH, *WqL, *WkH, *WkL, *WvH, *WvL;
    bf16 *QH, *QL, *KH, *KL, *VH, *VL, *VtH, *VtL, *PH, *PL;
    float* Sc;
    cudaGetSymbolAddress((void**)&XqH, gXqH);  cudaGetSymbolAddress((void**)&XqL, gXqL);
    cudaGetSymbolAddress((void**)&XkH, gXkH);  cudaGetSymbolAddress((void**)&XkL, gXkL);
    cudaGetSymbolAddress((void**)&XvH, gXvH);  cudaGetSymbolAddress((void**)&XvL, gXvL);
    cudaGetSymbolAddress((void**)&WqH, gWqH);  cudaGetSymbolAddress((void**)&WqL, gWqL);
    cudaGetSymbolAddress((void**)&WkH, gWkH);  cudaGetSymbolAddress((void**)&WkL, gWkL);
    cudaGetSymbolAddress((void**)&WvH, gWvH);  cudaGetSymbolAddress((void**)&WvL, gWvL);
    cudaGetSymbolAddress((void**)&QH,  gQH);   cudaGetSymbolAddress((void**)&QL,  gQL);
    cudaGetSymbolAddress((void**)&KH,  gKH);   cudaGetSymbolAddress((void**)&KL,  gKL);
    cudaGetSymbolAddress((void**)&VH,  gVH);   cudaGetSymbolAddress((void**)&VL,  gVL);
    cudaGetSymbolAddress((void**)&VtH, gVtH);  cudaGetSymbolAddress((void**)&VtL, gVtL);
    cudaGetSymbolAddress((void**)&PH,  gPH);   cudaGetSymbolAddress((void**)&PL,  gPL);
    cudaGetSymbolAddress((void**)&Sc,  gScores);

    cudaFuncSetAttribute(mma_gemm<0>, cudaFuncAttributeMaxDynamicSharedMemorySize, SMEM_DYN);
    cudaFuncSetAttribute(mma_gemm<1>, cudaFuncAttributeMaxDynamicSharedMemorySize, SMEM_DYN);

    const int M = B_ * S_;                  // 16384
    const float inv_sqrt_d = 1.0f / 32.0f;  // 1/sqrt(1024)

    // 1) split inputs + weights to bf16 hi/lo
    {
        int n4 = M * D_ / 4;
        split_kernel<<<n4 / 256, 256>>>((const float4*)query, (uint2*)XqH, (uint2*)XqL);
        split_kernel<<<n4 / 256, 256>>>((const float4*)key,   (uint2*)XkH, (uint2*)XkL);
        split_kernel<<<n4 / 256, 256>>>((const float4*)value, (uint2*)XvH, (uint2*)XvL);
        int w4 = D_ * D_ / 4;
        split_kernel<<<w4 / 256, 256>>>((const float4*)Wq, (uint2*)WqH, (uint2*)WqL);
        split_kernel<<<w4 / 256, 256>>>((const float4*)Wk, (uint2*)WkH, (uint2*)WkL);
        split_kernel<<<w4 / 256, 256>>>((const float4*)Wv, (uint2*)WvH, (uint2*)WvL);
    }

    // 2) projections (split-bf16 out; Q pre-scaled by 1/sqrt(D))
    {
        dim3 g(D_ / 128, M / 128, 1);       // (8, 128)
        mma_gemm<1><<<g, 256, SMEM_DYN>>>(XqH, XqL, WqH, WqL, bq, inv_sqrt_d,
                                          nullptr, QH, QL, M, D_, D_, 0, 0, 0);
        mma_gemm<1><<<g, 256, SMEM_DYN>>>(XkH, XkL, WkH, WkL, bk, 1.0f,
                                          nullptr, KH, KL, M, D_, D_, 0, 0, 0);
        mma_gemm<1><<<g, 256, SMEM_DYN>>>(XvH, XvL, WvH, WvL, bv, 1.0f,
                                          nullptr, VH, VL, M, D_, D_, 0, 0, 0);
    }

    // 3) transpose V per batch: [S,D] -> [D,S]
    {
        dim3 g(D_ / 32, S_ / 32, B_);
        transpose2_kernel<<<g, 256>>>(VH, VL, VtH, VtL);
    }

    // 4) scores = Q K^T (per batch), fp32 out
    {
        dim3 g(S_ / 128, S_ / 128, B_);     // (16, 16, 8)
        mma_gemm<0><<<g, 256, SMEM_DYN>>>(QH, QL, KH, KL, nullptr, 1.0f,
                                          Sc, nullptr, nullptr, S_, S_, D_,
                                          (long long)S_ * D_, (long long)S_ * D_,
                                          (long long)S_ * S_);
    }

    // 5) masked softmax -> split-bf16 P
    softmax_kernel<<<B_ * S_, 256>>>(Sc, mask, PH, PL);

    // 6) out = P V (per batch) via NT with V^T
    {
        dim3 g(D_ / 128, S_ / 128, B_);     // (8, 16, 8)
        mma_gemm<0><<<g, 256, SMEM_DYN>>>(PH, PL, VtH, VtL, nullptr, 1.0f,
                                          out, nullptr, nullptr, S_, D_, S_,
                                          (long long)S_ * S_, (long long)S_ * D_,
                                          (long long)S_ * D_);
    }
}

// round 6
// speedup vs baseline: 3.1967x; 2.0408x over previous
#include <cuda_runtime.h>
#include <cuda_fp16.h>
#include <math_constants.h>
#include <cstdint>

// ---------------------------------------------------------------------------
// Problem constants
// ---------------------------------------------------------------------------
#define B_ 8
#define S_ 2048
#define D_ 1024

typedef __half fp16;

// ---------------------------------------------------------------------------
// Scratch (device globals; allocation-free rule)
// ---------------------------------------------------------------------------
// rounded fp16 inputs (A operands of projections; exact side is W, split)
__device__ fp16 gXq[B_*S_*D_], gXk[B_*S_*D_], gXv[B_*S_*D_];
// split weights [N,K] row-major (torch Linear layout)
__device__ fp16 gWqH[D_*D_], gWqL[D_*D_];
__device__ fp16 gWkH[D_*D_], gWkL[D_*D_];
__device__ fp16 gWvH[D_*D_], gWvL[D_*D_];
// projection outputs: Q single (rounded side of scores GEMM), K split, V split
__device__ fp16 gQ[B_*S_*D_];
__device__ fp16 gKH[B_*S_*D_], gKL[B_*S_*D_];
__device__ fp16 gVH[B_*S_*D_], gVL[B_*S_*D_];
// V transposed per batch: [B][D][S], split
__device__ fp16 gVtH[B_*S_*D_], gVtL[B_*S_*D_];
// scores fp32 (unscaled), probs single fp16
__device__ float gScores[B_*S_*S_];
__device__ fp16 gP[(long long)B_*S_*S_];

// ---------------------------------------------------------------------------
// PTX helpers (sm_80-baseline only: cp.async, ldmatrix, mma.sync)
// ---------------------------------------------------------------------------
__device__ __forceinline__ uint32_t smem_u32(const void* p) {
    uint32_t a;
    asm("{ .reg .u64 t; cvta.to.shared.u64 t, %1; cvt.u32.u64 %0, t; }" : "=r"(a) : "l"(p));
    return a;
}
__device__ __forceinline__ void cp16(uint32_t dst, const void* src) {
    asm volatile("cp.async.cg.shared.global [%0], [%1], 16;"
                 :: "r"(dst), "l"(__cvta_generic_to_global(src)) : "memory");
}
#define CP_COMMIT() asm volatile("cp.async.commit_group;" ::: "memory")
#define CP_WAIT(n)  asm volatile("cp.async.wait_group %0;" :: "n"(n) : "memory")

__device__ __forceinline__ void ldm_x4(uint32_t* r, uint32_t addr) {
    asm volatile("ldmatrix.sync.aligned.m8n8.x4.shared.b16 {%0,%1,%2,%3}, [%4];"
                 : "=r"(r[0]), "=r"(r[1]), "=r"(r[2]), "=r"(r[3]) : "r"(addr));
}
__device__ __forceinline__ void mma_fp16(float* d, const uint32_t* a, const uint32_t* b) {
    asm volatile("mma.sync.aligned.m16n8k16.row.col.f32.f16.f16.f32 "
                 "{%0,%1,%2,%3}, {%4,%5,%6,%7}, {%8,%9}, {%0,%1,%2,%3};"
                 : "+f"(d[0]), "+f"(d[1]), "+f"(d[2]), "+f"(d[3])
                 : "r"(a[0]), "r"(a[1]), "r"(a[2]), "r"(a[3]), "r"(b[0]), "r"(b[1]));
}

// ---------------------------------------------------------------------------
// GEMM: C[M,N] = A[M,K] * (Bh+Bl)[N,K]^T, 2-pass fp16, mma.sync
// Tile 128x128, BK=32, 8 warps (2m x 4n, each 64x32), 4-stage cp.async.
// SMEM rows: 32 fp16 = 64B data at 80B stride (conflict-free ldmatrix).
// EPI==0: fp32 store. EPI==1: single-fp16 store of acc+bias.
// EPI==2: split-fp16 store of acc+bias.
// ---------------------------------------------------------------------------
#define BK_ 32
#define ROWB 80
#define MATB (128 * ROWB)          // 10240
#define STAGEB (3 * MATB)          // 30720 (A, Bh, Bl)
#define NSTAGE 4
#define SMEM_DYN (NSTAGE * STAGEB) // 122880

__device__ __forceinline__ void load_stage(uint32_t sbase, int slot, int tid,
                                           const fp16* A,
                                           const fp16* Bh, const fp16* Bl,
                                           int bm, int bn, int K, int k0)
{
    uint32_t sb = sbase + (uint32_t)slot * STAGEB;
#pragma unroll
    for (int t = 0; t < 2; t++) {
        int u = tid + 256 * t;              // 0..511
        int row = u >> 2;                   // 0..127
        int c = (u & 3) * 16;               // byte offset within 64B row
        uint32_t so = (uint32_t)(row * ROWB + c);
        size_t gA = (size_t)(bm + row) * K + k0 + (c >> 1);
        size_t gB = (size_t)(bn + row) * K + k0 + (c >> 1);
        cp16(sb + so,            A  + gA);
        cp16(sb + MATB + so,     Bh + gB);
        cp16(sb + 2 * MATB + so, Bl + gB);
    }
    CP_COMMIT();
}

template <int EPI>
__global__ __launch_bounds__(256, 1)
void mma_gemm(const fp16* __restrict__ A,
              const fp16* __restrict__ Bh, const fp16* __restrict__ Bl,
              const float* __restrict__ bias,
              float* __restrict__ Cf, fp16* __restrict__ Ch, fp16* __restrict__ Cl,
              int M, int N, int K,
              long long sA, long long sB, long long sC)
{
    extern __shared__ char smem[];
    const int tid  = threadIdx.x;
    const int wid  = tid >> 5;
    const int lane = tid & 31;

    const int bz = blockIdx.z;
    A  += (long long)bz * sA;
    Bh += (long long)bz * sB;  Bl += (long long)bz * sB;

    const int bm = blockIdx.y * 128;
    const int bn = blockIdx.x * 128;
    const int wm = (wid >> 2) * 64;
    const int wn = (wid & 3) * 32;

    const uint32_t sbase = smem_u32(smem);

    float acc[4][4][4];
#pragma unroll
    for (int i = 0; i < 4; i++)
#pragma unroll
        for (int j = 0; j < 4; j++)
#pragma unroll
            for (int q = 0; q < 4; q++) acc[i][j][q] = 0.f;

    const int NITER = K / BK_;

    load_stage(sbase, 0, tid, A, Bh, Bl, bm, bn, K, 0);
    load_stage(sbase, 1, tid, A, Bh, Bl, bm, bn, K, BK_);
    load_stage(sbase, 2, tid, A, Bh, Bl, bm, bn, K, 2 * BK_);

    const int a_row = lane & 15;
    const int a_k16 = (lane >> 4) * 16;
    const int b_row = (lane & 7) + ((lane >> 4) << 3);
    const int b_k16 = ((lane >> 3) & 1) * 16;

    for (int i = 0; i < NITER; i++) {
        if (i < NITER - 2)       CP_WAIT(2);
        else if (i == NITER - 2) CP_WAIT(1);
        else                     CP_WAIT(0);
        __syncthreads();

        if (i + 3 < NITER)
            load_stage(sbase, (i + 3) & 3, tid, A, Bh, Bl, bm, bn, K, (i + 3) * BK_);

        uint32_t st = sbase + (uint32_t)(i & 3) * STAGEB;
#pragma unroll
        for (int ks = 0; ks < 2; ks++) {
            const int kb = ks * 32;
            uint32_t af[4][4];
#pragma unroll
            for (int mf = 0; mf < 4; mf++) {
                uint32_t ra = st + (uint32_t)((wm + mf * 16 + a_row) * ROWB + kb + a_k16);
                ldm_x4(af[mf], ra);
            }
            uint32_t bh[4][2], bl[4][2];
#pragma unroll
            for (int np = 0; np < 2; np++) {
                uint32_t rb = st + MATB +
                              (uint32_t)((wn + np * 16 + b_row) * ROWB + kb + b_k16);
                uint32_t th[4], tl[4];
                ldm_x4(th, rb);
                ldm_x4(tl, rb + MATB);
                bh[np*2][0]   = th[0]; bh[np*2][1]   = th[1];
                bh[np*2+1][0] = th[2]; bh[np*2+1][1] = th[3];
                bl[np*2][0]   = tl[0]; bl[np*2][1]   = tl[1];
                bl[np*2+1][0] = tl[2]; bl[np*2+1][1] = tl[3];
            }
#pragma unroll
            for (int mf = 0; mf < 4; mf++)
#pragma unroll
                for (int nf = 0; nf < 4; nf++) {
                    mma_fp16(acc[mf][nf], af[mf], bh[nf]);
                    mma_fp16(acc[mf][nf], af[mf], bl[nf]);
                }
        }
    }

    // ---- epilogue (register -> global) ----
    const int rr = lane >> 2;
    const int cc = (lane & 3) * 2;
#pragma unroll
    for (int mf = 0; mf < 4; mf++) {
#pragma unroll
        for (int nf = 0; nf < 4; nf++) {
            const int row = bm + wm + mf * 16 + rr;
            const int col = bn + wn + nf * 8 + cc;
            float* a4 = acc[mf][nf];
            if (EPI == 0) {
                float* dst = Cf + (long long)bz * sC;
                *(float2*)&dst[(size_t)row * N + col]       = make_float2(a4[0], a4[1]);
                *(float2*)&dst[(size_t)(row + 8) * N + col] = make_float2(a4[2], a4[3]);
            } else {
                float b0 = bias[col], b1 = bias[col + 1];
                float v0 = a4[0] + b0, v1 = a4[1] + b1;
                float v2 = a4[2] + b0, v3 = a4[3] + b1;
                fp16 h0 = __float2half_rn(v0), h1 = __float2half_rn(v1);
                fp16 h2 = __float2half_rn(v2), h3 = __float2half_rn(v3);
                __half2 p0; p0.x = h0; p0.y = h1;
                __half2 p1; p1.x = h2; p1.y = h3;
                *(__half2*)&Ch[(size_t)row * N + col]       = p0;
                *(__half2*)&Ch[(size_t)(row + 8) * N + col] = p1;
                if (EPI == 2) {
                    fp16 l0 = __float2half_rn(v0 - __half2float(h0));
                    fp16 l1 = __float2half_rn(v1 - __half2float(h1));
                    fp16 l2 = __float2half_rn(v2 - __half2float(h2));
                    fp16 l3 = __float2half_rn(v3 - __half2float(h3));
                    __half2 q0; q0.x = l0; q0.y = l1;
                    __half2 q1; q1.x = l2; q1.y = l3;
                    *(__half2*)&Cl[(size_t)row * N + col]       = q0;
                    *(__half2*)&Cl[(size_t)(row + 8) * N + col] = q1;
                }
            }
        }
    }
}

// ---------------------------------------------------------------------------
// Prep: round all three X inputs fp32 -> fp16 (one launch)
// ---------------------------------------------------------------------------
#define XBLK (B_ * S_ * D_ / 4 / 256)      // blocks per tensor = 16384
__global__ __launch_bounds__(256)
void round3_kernel(const float4* __restrict__ q, const float4* __restrict__ k,
                   const float4* __restrict__ v,
                   uint2* __restrict__ oq, uint2* __restrict__ ok,
                   uint2* __restrict__ ov)
{
    int bb = blockIdx.x;
    const float4* src; uint2* dst;
    if (bb < XBLK)            { src = q; dst = oq; }
    else if (bb < 2 * XBLK)   { src = k; dst = ok; bb -= XBLK; }
    else                      { src = v; dst = ov; bb -= 2 * XBLK; }
    int i = bb * 256 + threadIdx.x;
    float4 x = src[i];
    __align__(8) fp16 h[4];
    h[0] = __float2half_rn(x.x); h[1] = __float2half_rn(x.y);
    h[2] = __float2half_rn(x.z); h[3] = __float2half_rn(x.w);
    dst[i] = *(uint2*)h;
}

// ---------------------------------------------------------------------------
// Prep: split all three W matrices fp32 -> fp16 hi/lo (one launch)
// ---------------------------------------------------------------------------
#define WBLK (D_ * D_ / 4 / 256)           // blocks per matrix = 1024
__global__ __launch_bounds__(256)
void splitW3_kernel(const float4* __restrict__ wq, const float4* __restrict__ wk,
                    const float4* __restrict__ wv,
                    uint2* __restrict__ qh, uint2* __restrict__ ql,
                    uint2* __restrict__ kh, uint2* __restrict__ kl,
                    uint2* __restrict__ vh, uint2* __restrict__ vl)
{
    int bb = blockIdx.x;
    const float4* src; uint2 *dh, *dl;
    if (bb < WBLK)          { src = wq; dh = qh; dl = ql; }
    else if (bb < 2 * WBLK) { src = wk; dh = kh; dl = kl; bb -= WBLK; }
    else                    { src = wv; dh = vh; dl = vl; bb -= 2 * WBLK; }
    int i = bb * 256 + threadIdx.x;
    float4 x = src[i];
    float f[4] = {x.x, x.y, x.z, x.w};
    __align__(8) fp16 h[4], l[4];
#pragma unroll
    for (int q = 0; q < 4; q++) {
        h[q] = __float2half_rn(f[q]);
        l[q] = __float2half_rn(f[q] - __half2float(h[q]));
    }
    dh[i] = *(uint2*)h;
    dl[i] = *(uint2*)l;
}

// ---------------------------------------------------------------------------
// per-batch transpose of split V: [B][S][D] -> [B][D][S]
// ---------------------------------------------------------------------------
__global__ __launch_bounds__(256)
void transpose2_kernel(const fp16* __restrict__ srcH, const fp16* __restrict__ srcL,
                       fp16* __restrict__ dstH, fp16* __restrict__ dstL)
{
    __shared__ fp16 tH[32][33];
    __shared__ fp16 tL[32][33];
    const int b = blockIdx.z;
    const int x0 = blockIdx.x * 32;   // D dim
    const int y0 = blockIdx.y * 32;   // S dim
    const int tx = threadIdx.x & 31;
    const int ty = threadIdx.x >> 5;  // 0..7
    const fp16* sH = srcH + (size_t)b * S_ * D_;
    const fp16* sL = srcL + (size_t)b * S_ * D_;
    fp16* dH = dstH + (size_t)b * S_ * D_;
    fp16* dL = dstL + (size_t)b * S_ * D_;
#pragma unroll
    for (int j = 0; j < 4; j++) {
        int r = ty + j * 8;
        tH[r][tx] = sH[(size_t)(y0 + r) * D_ + x0 + tx];
        tL[r][tx] = sL[(size_t)(y0 + r) * D_ + x0 + tx];
    }
    __syncthreads();
#pragma unroll
    for (int j = 0; j < 4; j++) {
        int r = ty + j * 8;
        dH[(size_t)(x0 + r) * S_ + y0 + tx] = tH[tx][r];
        dL[(size_t)(x0 + r) * S_ + y0 + tx] = tL[tx][r];
    }
}

// ---------------------------------------------------------------------------
// Masked softmax: fp32 raw scores (unscaled) -> single fp16 prob row.
// Applies 1/sqrt(D) scale here.
// ---------------------------------------------------------------------------
__global__ __launch_bounds__(256)
void softmax_kernel(const float* __restrict__ scores, const int* __restrict__ mask,
                    fp16* __restrict__ P)
{
    const int row = blockIdx.x;               // 0..B*S-1
    const int b   = row / S_;
    const float* p = scores + (long long)row * S_;
    const int* mrow = mask + (long long)b * S_;

    const int tid = threadIdx.x;
    const int c0 = tid * 8;
    const float sc = 1.0f / 32.0f;            // 1/sqrt(1024)

    float4 v0 = *(const float4*)&p[c0];
    float4 v1 = *(const float4*)&p[c0 + 4];
    int4 m0 = *(const int4*)&mrow[c0];
    int4 m1 = *(const int4*)&mrow[c0 + 4];

    float v[8]  = {v0.x * sc, v0.y * sc, v0.z * sc, v0.w * sc,
                   v1.x * sc, v1.y * sc, v1.z * sc, v1.w * sc};
    int   mk[8] = {m0.x, m0.y, m0.z, m0.w, m1.x, m1.y, m1.z, m1.w};

    float mx = -CUDART_INF_F;
#pragma unroll
    for (int i = 0; i < 8; i++)
        if (mk[i]) mx = fmaxf(mx, v[i]);
#pragma unroll
    for (int o = 16; o > 0; o >>= 1)
        mx = fmaxf(mx, __shfl_xor_sync(0xFFFFFFFFu, mx, o));

    __shared__ float sred[8];
    if ((tid & 31) == 0) sred[tid >> 5] = mx;
    __syncthreads();
    mx = sred[0];
#pragma unroll
    for (int w = 1; w < 8; w++) mx = fmaxf(mx, sred[w]);
    __syncthreads();

    const float mxs = (mx > -CUDART_INF_F) ? mx : 0.f;

    float sum = 0.f;
#pragma unroll
    for (int i = 0; i < 8; i++) {
        float e = mk[i] ? __expf(v[i] - mxs) : 0.f;
        v[i] = e;
        sum += e;
    }
#pragma unroll
    for (int o = 16; o > 0; o >>= 1)
        sum += __shfl_xor_sync(0xFFFFFFFFu, sum, o);
    if ((tid & 31) == 0) sred[tid >> 5] = sum;
    __syncthreads();
    sum = 0.f;
#pragma unroll
    for (int w = 0; w < 8; w++) sum += sred[w];

    const float inv = (sum > 0.f) ? (1.f / sum) : 0.f;

    __align__(16) fp16 hh[8];
#pragma unroll
    for (int i = 0; i < 8; i++)
        hh[i] = __float2half_rn(v[i] * inv);
    *(uint4*)&P[(long long)row * S_ + c0] = *(uint4*)hh;
}

// ---------------------------------------------------------------------------
// Launch
// ---------------------------------------------------------------------------
extern "C" void kernel_launch(void* const* d_in, const int* in_sizes, int n_in,
                              void* d_out, int out_size)
{
    const float* query = (const float*)d_in[0];
    const float* key   = (const float*)d_in[1];
    const float* value = (const float*)d_in[2];
    const int*   mask  = (const int*)  d_in[3];
    const float* Wq    = (const float*)d_in[4];
    const float* bq    = (const float*)d_in[5];
    const float* Wk    = (const float*)d_in[6];
    const float* bk    = (const float*)d_in[7];
    const float* Wv    = (const float*)d_in[8];
    const float* bv    = (const float*)d_in[9];
    float* out = (float*)d_out;

    fp16 *Xq, *Xk, *Xv;
    fp16 *WqH, *WqL, *WkH, *WkL, *WvH, *WvL;
    fp16 *Q, *KH, *KL, *VH, *VL, *VtH, *VtL, *P;
    float* Sc;
    cudaGetSymbolAddress((void**)&Xq,  gXq);
    cudaGetSymbolAddress((void**)&Xk,  gXk);
    cudaGetSymbolAddress((void**)&Xv,  gXv);
    cudaGetSymbolAddress((void**)&WqH, gWqH);  cudaGetSymbolAddress((void**)&WqL, gWqL);
    cudaGetSymbolAddress((void**)&WkH, gWkH);  cudaGetSymbolAddress((void**)&WkL, gWkL);
    cudaGetSymbolAddress((void**)&WvH, gWvH);  cudaGetSymbolAddress((void**)&WvL, gWvL);
    cudaGetSymbolAddress((void**)&Q,   gQ);
    cudaGetSymbolAddress((void**)&KH,  gKH);   cudaGetSymbolAddress((void**)&KL,  gKL);
    cudaGetSymbolAddress((void**)&VH,  gVH);   cudaGetSymbolAddress((void**)&VL,  gVL);
    cudaGetSymbolAddress((void**)&VtH, gVtH);  cudaGetSymbolAddress((void**)&VtL, gVtL);
    cudaGetSymbolAddress((void**)&P,   gP);
    cudaGetSymbolAddress((void**)&Sc,  gScores);

    cudaFuncSetAttribute(mma_gemm<0>, cudaFuncAttributeMaxDynamicSharedMemorySize, SMEM_DYN);
    cudaFuncSetAttribute(mma_gemm<1>, cudaFuncAttributeMaxDynamicSharedMemorySize, SMEM_DYN);
    cudaFuncSetAttribute(mma_gemm<2>, cudaFuncAttributeMaxDynamicSharedMemorySize, SMEM_DYN);

    const int M = B_ * S_;                  // 16384

    // launch 0: round inputs to fp16
    round3_kernel<<<3 * XBLK, 256>>>((const float4*)query, (const float4*)key,
                                     (const float4*)value,
                                     (uint2*)Xq, (uint2*)Xk, (uint2*)Xv);
    // launch 1: split weights to fp16 hi/lo
    splitW3_kernel<<<3 * WBLK, 256>>>((const float4*)Wq, (const float4*)Wk,
                                      (const float4*)Wv,
                                      (uint2*)WqH, (uint2*)WqL,
                                      (uint2*)WkH, (uint2*)WkL,
                                      (uint2*)WvH, (uint2*)WvL);

    // launches 2-4: projections (X rounded; W exact via split)
    {
        dim3 g(D_ / 128, M / 128, 1);       // (8, 128)
        mma_gemm<1><<<g, 256, SMEM_DYN>>>(Xq, WqH, WqL, bq,
                                          nullptr, Q, nullptr, M, D_, D_, 0, 0, 0);
        mma_gemm<2><<<g, 256, SMEM_DYN>>>(Xk, WkH, WkL, bk,
                                          nullptr, KH, KL, M, D_, D_, 0, 0, 0);
        mma_gemm<2><<<g, 256, SMEM_DYN>>>(Xv, WvH, WvL, bv,
                                          nullptr, VH, VL, M, D_, D_, 0, 0, 0);
    }

    // launch 5 (ncu profiles this one): scores = Q K^T per batch, fp32 out
    {
        dim3 g(S_ / 128, S_ / 128, B_);     // (16, 16, 8)
        mma_gemm<0><<<g, 256, SMEM_DYN>>>(Q, KH, KL, nullptr,
                                          Sc, nullptr, nullptr, S_, S_, D_,
                                          (long long)S_ * D_, (long long)S_ * D_,
                                          (long long)S_ * S_);
    }

    // launch 6: transpose V per batch: [S,D] -> [D,S]
    {
        dim3 g(D_ / 32, S_ / 32, B_);
        transpose2_kernel<<<g, 256>>>(VH, VL, VtH, VtL);
    }

    // launch 7: masked softmax (applies 1/sqrt(D)) -> single fp16 P
    softmax_kernel<<<B_ * S_, 256>>>(Sc, mask, P);

    // launch 8: out = P V per batch (NT with V^T; P rounded, Vt exact via split)
    {
        dim3 g(D_ / 128, S_ / 128, B_);     // (8, 16, 8)
        mma_gemm<0><<<g, 256, SMEM_DYN>>>(P, VtH, VtL, nullptr,
                                          out, nullptr, nullptr, S_, D_, S_,
                                          (long long)S_ * S_, (long long)S_ * D_,
                                          (long long)S_ * D_);
    }
}

// round 7
// speedup vs baseline: 4.2049x; 1.3154x over previous
#include <cuda_runtime.h>
#include <cuda_fp16.h>
#include <math_constants.h>
#include <cstdint>

// ---------------------------------------------------------------------------
// Problem constants
// ---------------------------------------------------------------------------
#define B_ 8
#define S_ 2048
#define D_ 1024

typedef __half fp16;

// ---------------------------------------------------------------------------
// Scratch (device globals; allocation-free rule)
// ---------------------------------------------------------------------------
__device__ fp16 gXq[B_*S_*D_], gXk[B_*S_*D_], gXv[B_*S_*D_];
__device__ fp16 gWq[D_*D_], gWk[D_*D_], gWv[D_*D_];
__device__ fp16 gQ[B_*S_*D_], gK[B_*S_*D_], gV[B_*S_*D_];
__device__ fp16 gVt[B_*S_*D_];                // [B][D][S]
__device__ float gScores[B_*S_*S_];
__device__ fp16 gP[(long long)B_*S_*S_];

// ---------------------------------------------------------------------------
// PTX helpers (sm_80-baseline: cp.async, ldmatrix, mma.sync)
// ---------------------------------------------------------------------------
__device__ __forceinline__ uint32_t smem_u32(const void* p) {
    uint32_t a;
    asm("{ .reg .u64 t; cvta.to.shared.u64 t, %1; cvt.u32.u64 %0, t; }" : "=r"(a) : "l"(p));
    return a;
}
__device__ __forceinline__ void cp16(uint32_t dst, const void* src) {
    asm volatile("cp.async.cg.shared.global [%0], [%1], 16;"
                 :: "r"(dst), "l"(__cvta_generic_to_global(src)) : "memory");
}
#define CP_COMMIT() asm volatile("cp.async.commit_group;" ::: "memory")
#define CP_WAIT(n)  asm volatile("cp.async.wait_group %0;" :: "n"(n) : "memory")

__device__ __forceinline__ void ldm_x4(uint32_t* r, uint32_t addr) {
    asm volatile("ldmatrix.sync.aligned.m8n8.x4.shared.b16 {%0,%1,%2,%3}, [%4];"
                 : "=r"(r[0]), "=r"(r[1]), "=r"(r[2]), "=r"(r[3]) : "r"(addr));
}
__device__ __forceinline__ void mma_fp16(float* d, const uint32_t* a, const uint32_t* b) {
    asm volatile("mma.sync.aligned.m16n8k16.row.col.f32.f16.f16.f32 "
                 "{%0,%1,%2,%3}, {%4,%5,%6,%7}, {%8,%9}, {%0,%1,%2,%3};"
                 : "+f"(d[0]), "+f"(d[1]), "+f"(d[2]), "+f"(d[3])
                 : "r"(a[0]), "r"(a[1]), "r"(a[2]), "r"(a[3]), "r"(b[0]), "r"(b[1]));
}

// ---------------------------------------------------------------------------
// GEMM: C[M,N] = A[M,K] * B[N,K]^T, single-pass fp16, mma.sync
// Tile 128x128, BK=32, 8 warps (2m x 4n, each 64x32), 4-stage cp.async.
// SMEM rows: 32 fp16 = 64B at 80B stride (conflict-free ldmatrix).
// EPI==0: fp32 store of acc. EPI==1: fp16 store of acc+bias.
// ---------------------------------------------------------------------------
#define BK_ 32
#define ROWB 80
#define MATB (128 * ROWB)          // 10240
#define STAGEB (2 * MATB)          // 20480 (A, B)
#define NSTAGE 4
#define SMEM_DYN (NSTAGE * STAGEB) // 81920 -> 2 CTAs/SM

__device__ __forceinline__ void load_stage(uint32_t sbase, int slot, int tid,
                                           const fp16* A, const fp16* Bm,
                                           int bm, int bn, int K, int k0)
{
    uint32_t sb = sbase + (uint32_t)slot * STAGEB;
#pragma unroll
    for (int t = 0; t < 2; t++) {
        int u = tid + 256 * t;              // 0..511
        int row = u >> 2;                   // 0..127
        int c = (u & 3) * 16;               // byte offset within 64B row
        uint32_t so = (uint32_t)(row * ROWB + c);
        size_t gA = (size_t)(bm + row) * K + k0 + (c >> 1);
        size_t gB = (size_t)(bn + row) * K + k0 + (c >> 1);
        cp16(sb + so,        A  + gA);
        cp16(sb + MATB + so, Bm + gB);
    }
    CP_COMMIT();
}

template <int EPI>
__global__ __launch_bounds__(256, 2)
void mma_gemm(const fp16* __restrict__ A, const fp16* __restrict__ Bm,
              const float* __restrict__ bias,
              float* __restrict__ Cf, fp16* __restrict__ Ch,
              int M, int N, int K,
              long long sA, long long sB, long long sC)
{
    extern __shared__ char smem[];
    const int tid  = threadIdx.x;
    const int wid  = tid >> 5;
    const int lane = tid & 31;

    const int bz = blockIdx.z;
    A  += (long long)bz * sA;
    Bm += (long long)bz * sB;

    const int bm = blockIdx.y * 128;
    const int bn = blockIdx.x * 128;
    const int wm = (wid >> 2) * 64;
    const int wn = (wid & 3) * 32;

    const uint32_t sbase = smem_u32(smem);

    float acc[4][4][4];
#pragma unroll
    for (int i = 0; i < 4; i++)
#pragma unroll
        for (int j = 0; j < 4; j++)
#pragma unroll
            for (int q = 0; q < 4; q++) acc[i][j][q] = 0.f;

    const int NITER = K / BK_;

    load_stage(sbase, 0, tid, A, Bm, bm, bn, K, 0);
    load_stage(sbase, 1, tid, A, Bm, bm, bn, K, BK_);
    load_stage(sbase, 2, tid, A, Bm, bm, bn, K, 2 * BK_);

    const int a_row = lane & 15;
    const int a_k16 = (lane >> 4) * 16;
    const int b_row = (lane & 7) + ((lane >> 4) << 3);
    const int b_k16 = ((lane >> 3) & 1) * 16;

    for (int i = 0; i < NITER; i++) {
        if (i < NITER - 2)       CP_WAIT(2);
        else if (i == NITER - 2) CP_WAIT(1);
        else                     CP_WAIT(0);
        __syncthreads();

        if (i + 3 < NITER)
            load_stage(sbase, (i + 3) & 3, tid, A, Bm, bm, bn, K, (i + 3) * BK_);

        uint32_t st = sbase + (uint32_t)(i & 3) * STAGEB;
#pragma unroll
        for (int ks = 0; ks < 2; ks++) {
            const int kb = ks * 32;
            uint32_t af[4][4];
#pragma unroll
            for (int mf = 0; mf < 4; mf++) {
                uint32_t ra = st + (uint32_t)((wm + mf * 16 + a_row) * ROWB + kb + a_k16);
                ldm_x4(af[mf], ra);
            }
            uint32_t bf[4][2];
#pragma unroll
            for (int np = 0; np < 2; np++) {
                uint32_t rb = st + MATB +
                              (uint32_t)((wn + np * 16 + b_row) * ROWB + kb + b_k16);
                uint32_t th[4];
                ldm_x4(th, rb);
                bf[np*2][0]   = th[0]; bf[np*2][1]   = th[1];
                bf[np*2+1][0] = th[2]; bf[np*2+1][1] = th[3];
            }
#pragma unroll
            for (int mf = 0; mf < 4; mf++)
#pragma unroll
                for (int nf = 0; nf < 4; nf++)
                    mma_fp16(acc[mf][nf], af[mf], bf[nf]);
        }
    }

    // ---- epilogue (register -> global) ----
    const int rr = lane >> 2;
    const int cc = (lane & 3) * 2;
#pragma unroll
    for (int mf = 0; mf < 4; mf++) {
#pragma unroll
        for (int nf = 0; nf < 4; nf++) {
            const int row = bm + wm + mf * 16 + rr;
            const int col = bn + wn + nf * 8 + cc;
            float* a4 = acc[mf][nf];
            if (EPI == 0) {
                float* dst = Cf + (long long)bz * sC;
                *(float2*)&dst[(size_t)row * N + col]       = make_float2(a4[0], a4[1]);
                *(float2*)&dst[(size_t)(row + 8) * N + col] = make_float2(a4[2], a4[3]);
            } else {
                float b0 = bias[col], b1 = bias[col + 1];
                __half2 p0; p0.x = __float2half_rn(a4[0] + b0); p0.y = __float2half_rn(a4[1] + b1);
                __half2 p1; p1.x = __float2half_rn(a4[2] + b0); p1.y = __float2half_rn(a4[3] + b1);
                *(__half2*)&Ch[(size_t)row * N + col]       = p0;
                *(__half2*)&Ch[(size_t)(row + 8) * N + col] = p1;
            }
        }
    }
}

// ---------------------------------------------------------------------------
// Prep: round three fp32 tensors -> fp16 (one launch for X's, one for W's)
// ---------------------------------------------------------------------------
__global__ __launch_bounds__(256)
void round3_kernel(const float4* __restrict__ a, const float4* __restrict__ b,
                   const float4* __restrict__ c,
                   uint2* __restrict__ oa, uint2* __restrict__ ob,
                   uint2* __restrict__ oc, int blk_per)
{
    int bb = blockIdx.x;
    const float4* src; uint2* dst;
    if (bb < blk_per)            { src = a; dst = oa; }
    else if (bb < 2 * blk_per)   { src = b; dst = ob; bb -= blk_per; }
    else                         { src = c; dst = oc; bb -= 2 * blk_per; }
    int i = bb * 256 + threadIdx.x;
    float4 x = src[i];
    __align__(8) fp16 h[4];
    h[0] = __float2half_rn(x.x); h[1] = __float2half_rn(x.y);
    h[2] = __float2half_rn(x.z); h[3] = __float2half_rn(x.w);
    dst[i] = *(uint2*)h;
}
#define XBLK (B_ * S_ * D_ / 4 / 256)      // 16384
#define WBLK (D_ * D_ / 4 / 256)           // 1024

// ---------------------------------------------------------------------------
// per-batch transpose of V: [B][S][D] -> [B][D][S]
// ---------------------------------------------------------------------------
__global__ __launch_bounds__(256)
void transpose_kernel(const fp16* __restrict__ src, fp16* __restrict__ dst)
{
    __shared__ fp16 t[32][33];
    const int b = blockIdx.z;
    const int x0 = blockIdx.x * 32;   // D dim
    const int y0 = blockIdx.y * 32;   // S dim
    const int tx = threadIdx.x & 31;
    const int ty = threadIdx.x >> 5;  // 0..7
    const fp16* s = src + (size_t)b * S_ * D_;
    fp16* d = dst + (size_t)b * S_ * D_;
#pragma unroll
    for (int j = 0; j < 4; j++) {
        int r = ty + j * 8;
        t[r][tx] = s[(size_t)(y0 + r) * D_ + x0 + tx];
    }
    __syncthreads();
#pragma unroll
    for (int j = 0; j < 4; j++) {
        int r = ty + j * 8;
        d[(size_t)(x0 + r) * S_ + y0 + tx] = t[tx][r];
    }
}

// ---------------------------------------------------------------------------
// Masked softmax: fp32 raw scores (unscaled) -> fp16 prob row; applies 1/32.
// ---------------------------------------------------------------------------
__global__ __launch_bounds__(256)
void softmax_kernel(const float* __restrict__ scores, const int* __restrict__ mask,
                    fp16* __restrict__ P)
{
    const int row = blockIdx.x;               // 0..B*S-1
    const int b   = row / S_;
    const float* p = scores + (long long)row * S_;
    const int* mrow = mask + (long long)b * S_;

    const int tid = threadIdx.x;
    const int c0 = tid * 8;
    const float sc = 1.0f / 32.0f;            // 1/sqrt(1024)

    float4 v0 = *(const float4*)&p[c0];
    float4 v1 = *(const float4*)&p[c0 + 4];
    int4 m0 = *(const int4*)&mrow[c0];
    int4 m1 = *(const int4*)&mrow[c0 + 4];

    float v[8]  = {v0.x * sc, v0.y * sc, v0.z * sc, v0.w * sc,
                   v1.x * sc, v1.y * sc, v1.z * sc, v1.w * sc};
    int   mk[8] = {m0.x, m0.y, m0.z, m0.w, m1.x, m1.y, m1.z, m1.w};

    float mx = -CUDART_INF_F;
#pragma unroll
    for (int i = 0; i < 8; i++)
        if (mk[i]) mx = fmaxf(mx, v[i]);
#pragma unroll
    for (int o = 16; o > 0; o >>= 1)
        mx = fmaxf(mx, __shfl_xor_sync(0xFFFFFFFFu, mx, o));

    __shared__ float sred[8];
    if ((tid & 31) == 0) sred[tid >> 5] = mx;
    __syncthreads();
    mx = sred[0];
#pragma unroll
    for (int w = 1; w < 8; w++) mx = fmaxf(mx, sred[w]);
    __syncthreads();

    const float mxs = (mx > -CUDART_INF_F) ? mx : 0.f;

    float sum = 0.f;
#pragma unroll
    for (int i = 0; i < 8; i++) {
        float e = mk[i] ? __expf(v[i] - mxs) : 0.f;
        v[i] = e;
        sum += e;
    }
#pragma unroll
    for (int o = 16; o > 0; o >>= 1)
        sum += __shfl_xor_sync(0xFFFFFFFFu, sum, o);
    if ((tid & 31) == 0) sred[tid >> 5] = sum;
    __syncthreads();
    sum = 0.f;
#pragma unroll
    for (int w = 0; w < 8; w++) sum += sred[w];

    const float inv = (sum > 0.f) ? (1.f / sum) : 0.f;

    __align__(16) fp16 hh[8];
#pragma unroll
    for (int i = 0; i < 8; i++)
        hh[i] = __float2half_rn(v[i] * inv);
    *(uint4*)&P[(long long)row * S_ + c0] = *(uint4*)hh;
}

// ---------------------------------------------------------------------------
// Launch
// ---------------------------------------------------------------------------
extern "C" void kernel_launch(void* const* d_in, const int* in_sizes, int n_in,
                              void* d_out, int out_size)
{
    const float* query = (const float*)d_in[0];
    const float* key   = (const float*)d_in[1];
    const float* value = (const float*)d_in[2];
    const int*   mask  = (const int*)  d_in[3];
    const float* Wq    = (const float*)d_in[4];
    const float* bq    = (const float*)d_in[5];
    const float* Wk    = (const float*)d_in[6];
    const float* bk    = (const float*)d_in[7];
    const float* Wv    = (const float*)d_in[8];
    const float* bv    = (const float*)d_in[9];
    float* out = (float*)d_out;

    fp16 *Xq, *Xk, *Xv, *Wqh, *Wkh, *Wvh;
    fp16 *Q, *K, *V, *Vt, *P;
    float* Sc;
    cudaGetSymbolAddress((void**)&Xq,  gXq);
    cudaGetSymbolAddress((void**)&Xk,  gXk);
    cudaGetSymbolAddress((void**)&Xv,  gXv);
    cudaGetSymbolAddress((void**)&Wqh, gWq);
    cudaGetSymbolAddress((void**)&Wkh, gWk);
    cudaGetSymbolAddress((void**)&Wvh, gWv);
    cudaGetSymbolAddress((void**)&Q,   gQ);
    cudaGetSymbolAddress((void**)&K,   gK);
    cudaGetSymbolAddress((void**)&V,   gV);
    cudaGetSymbolAddress((void**)&Vt,  gVt);
    cudaGetSymbolAddress((void**)&P,   gP);
    cudaGetSymbolAddress((void**)&Sc,  gScores);

    cudaFuncSetAttribute(mma_gemm<0>, cudaFuncAttributeMaxDynamicSharedMemorySize, SMEM_DYN);
    cudaFuncSetAttribute(mma_gemm<1>, cudaFuncAttributeMaxDynamicSharedMemorySize, SMEM_DYN);

    const int M = B_ * S_;                  // 16384

    // launch 0: round X inputs to fp16
    round3_kernel<<<3 * XBLK, 256>>>((const float4*)query, (const float4*)key,
                                     (const float4*)value,
                                     (uint2*)Xq, (uint2*)Xk, (uint2*)Xv, XBLK);
    // launch 1: round weights to fp16
    round3_kernel<<<3 * WBLK, 256>>>((const float4*)Wq, (const float4*)Wk,
                                     (const float4*)Wv,
                                     (uint2*)Wqh, (uint2*)Wkh, (uint2*)Wvh, WBLK);

    // launches 2-4: projections (fp16 out, bias in epilogue)
    {
        dim3 g(D_ / 128, M / 128, 1);       // (8, 128)
        mma_gemm<1><<<g, 256, SMEM_DYN>>>(Xq, Wqh, bq, nullptr, Q, M, D_, D_, 0, 0, 0);
        mma_gemm<1><<<g, 256, SMEM_DYN>>>(Xk, Wkh, bk, nullptr, K, M, D_, D_, 0, 0, 0);
        mma_gemm<1><<<g, 256, SMEM_DYN>>>(Xv, Wvh, bv, nullptr, V, M, D_, D_, 0, 0, 0);
    }

    // launch 5 (ncu profiles this): scores = Q K^T per batch, fp32 out
    {
        dim3 g(S_ / 128, S_ / 128, B_);     // (16, 16, 8)
        mma_gemm<0><<<g, 256, SMEM_DYN>>>(Q, K, nullptr, Sc, nullptr, S_, S_, D_,
                                          (long long)S_ * D_, (long long)S_ * D_,
                                          (long long)S_ * S_);
    }

    // launch 6: transpose V per batch: [S,D] -> [D,S]
    {
        dim3 g(D_ / 32, S_ / 32, B_);
        transpose_kernel<<<g, 256>>>(V, Vt);
    }

    // launch 7: masked softmax (applies 1/sqrt(D)) -> fp16 P
    softmax_kernel<<<B_ * S_, 256>>>(Sc, mask, P);

    // launch 8: out = P V per batch (NT with V^T)
    {
        dim3 g(D_ / 128, S_ / 128, B_);     // (8, 16, 8)
        mma_gemm<0><<<g, 256, SMEM_DYN>>>(P, Vt, nullptr, out, nullptr, S_, D_, S_,
                                          (long long)S_ * S_, (long long)S_ * D_,
                                          (long long)S_ * D_);
    }
}

// round 8
// speedup vs baseline: 6.4861x; 1.5425x over previous
#include <cuda_runtime.h>
#include <cuda_fp16.h>
#include <math_constants.h>
#include <cstdint>

// ---------------------------------------------------------------------------
// Problem constants
// ---------------------------------------------------------------------------
#define B_ 8
#define S_ 2048
#define D_ 1024

typedef __half fp16;

// ---------------------------------------------------------------------------
// Scratch (device globals; allocation-free rule)
// ---------------------------------------------------------------------------
__device__ fp16 gXq[B_*S_*D_], gXk[B_*S_*D_], gXv[B_*S_*D_];
__device__ fp16 gWq[D_*D_], gWk[D_*D_], gWv[D_*D_];
__device__ fp16 gQ[B_*S_*D_], gK[B_*S_*D_], gV[B_*S_*D_];
__device__ fp16 gVt[B_*S_*D_];                // [B][D][S]
__device__ float gScores[B_*S_*S_];
__device__ fp16 gP[(long long)B_*S_*S_];

// ---------------------------------------------------------------------------
// PTX helpers (sm_80-baseline: cp.async, ldmatrix, mma.sync)
// ---------------------------------------------------------------------------
__device__ __forceinline__ uint32_t smem_u32(const void* p) {
    uint32_t a;
    asm("{ .reg .u64 t; cvta.to.shared.u64 t, %1; cvt.u32.u64 %0, t; }" : "=r"(a) : "l"(p));
    return a;
}
__device__ __forceinline__ void cp16(uint32_t dst, const void* src) {
    asm volatile("cp.async.cg.shared.global [%0], [%1], 16;"
                 :: "r"(dst), "l"(__cvta_generic_to_global(src)) : "memory");
}
#define CP_COMMIT() asm volatile("cp.async.commit_group;" ::: "memory")
#define CP_WAIT(n)  asm volatile("cp.async.wait_group %0;" :: "n"(n) : "memory")

__device__ __forceinline__ void ldm_x4(uint32_t* r, uint32_t addr) {
    asm volatile("ldmatrix.sync.aligned.m8n8.x4.shared.b16 {%0,%1,%2,%3}, [%4];"
                 : "=r"(r[0]), "=r"(r[1]), "=r"(r[2]), "=r"(r[3]) : "r"(addr));
}
__device__ __forceinline__ void mma_fp16(float* d, const uint32_t* a, const uint32_t* b) {
    asm volatile("mma.sync.aligned.m16n8k16.row.col.f32.f16.f16.f32 "
                 "{%0,%1,%2,%3}, {%4,%5,%6,%7}, {%8,%9}, {%0,%1,%2,%3};"
                 : "+f"(d[0]), "+f"(d[1]), "+f"(d[2]), "+f"(d[3])
                 : "r"(a[0]), "r"(a[1]), "r"(a[2]), "r"(a[3]), "r"(b[0]), "r"(b[1]));
}

// ---------------------------------------------------------------------------
// GEMM: C[M,N] = A[M,K] * B[N,K]^T, single-pass fp16, mma.sync
// Tile 128x128, BK=32, 8 warps (2m x 4n, each 64x32), 4-stage cp.async,
// register-level fragment double buffering (ldmatrix ks+1 overlaps MMA ks).
// SMEM rows: 32 fp16 = 64B at 80B stride (conflict-free ldmatrix).
// EPI==0: fp32 store of acc. EPI==1: fp16 store of acc+bias.
// ---------------------------------------------------------------------------
#define BK_ 32
#define ROWB 80
#define MATB (128 * ROWB)          // 10240
#define STAGEB (2 * MATB)          // 20480 (A, B)
#define NSTAGE 4
#define SMEM_DYN (NSTAGE * STAGEB) // 81920 -> 2 CTAs/SM

struct Frag {
    uint32_t a[4][4];
    uint32_t b[4][2];
};

__device__ __forceinline__ void load_stage(uint32_t sbase, int slot, int tid,
                                           const fp16* A, const fp16* Bm,
                                           int bm, int bn, int K, int k0)
{
    uint32_t sb = sbase + (uint32_t)slot * STAGEB;
#pragma unroll
    for (int t = 0; t < 2; t++) {
        int u = tid + 256 * t;              // 0..511
        int row = u >> 2;                   // 0..127
        int c = (u & 3) * 16;               // byte offset within 64B row
        uint32_t so = (uint32_t)(row * ROWB + c);
        size_t gA = (size_t)(bm + row) * K + k0 + (c >> 1);
        size_t gB = (size_t)(bn + row) * K + k0 + (c >> 1);
        cp16(sb + so,        A  + gA);
        cp16(sb + MATB + so, Bm + gB);
    }
    CP_COMMIT();
}

__device__ __forceinline__ void load_frags(Frag& f, uint32_t st, int kb,
                                           int wm, int wn,
                                           int a_row, int a_k16,
                                           int b_row, int b_k16)
{
#pragma unroll
    for (int mf = 0; mf < 4; mf++) {
        uint32_t ra = st + (uint32_t)((wm + mf * 16 + a_row) * ROWB + kb + a_k16);
        ldm_x4(f.a[mf], ra);
    }
#pragma unroll
    for (int np = 0; np < 2; np++) {
        uint32_t rb = st + MATB +
                      (uint32_t)((wn + np * 16 + b_row) * ROWB + kb + b_k16);
        uint32_t th[4];
        ldm_x4(th, rb);
        f.b[np*2][0]   = th[0]; f.b[np*2][1]   = th[1];
        f.b[np*2+1][0] = th[2]; f.b[np*2+1][1] = th[3];
    }
}

__device__ __forceinline__ void run_mmas(float acc[4][4][4], const Frag& f)
{
#pragma unroll
    for (int mf = 0; mf < 4; mf++)
#pragma unroll
        for (int nf = 0; nf < 4; nf++)
            mma_fp16(acc[mf][nf], f.a[mf], f.b[nf]);
}

template <int EPI>
__global__ __launch_bounds__(256, 2)
void mma_gemm(const fp16* __restrict__ A, const fp16* __restrict__ Bm,
              const float* __restrict__ bias,
              float* __restrict__ Cf, fp16* __restrict__ Ch,
              int M, int N, int K,
              long long sA, long long sB, long long sC)
{
    extern __shared__ char smem[];
    const int tid  = threadIdx.x;
    const int wid  = tid >> 5;
    const int lane = tid & 31;

    const int bz = blockIdx.z;
    A  += (long long)bz * sA;
    Bm += (long long)bz * sB;

    const int bm = blockIdx.y * 128;
    const int bn = blockIdx.x * 128;
    const int wm = (wid >> 2) * 64;
    const int wn = (wid & 3) * 32;

    const uint32_t sbase = smem_u32(smem);

    float acc[4][4][4];
#pragma unroll
    for (int i = 0; i < 4; i++)
#pragma unroll
        for (int j = 0; j < 4; j++)
#pragma unroll
            for (int q = 0; q < 4; q++) acc[i][j][q] = 0.f;

    const int NITER = K / BK_;

    load_stage(sbase, 0, tid, A, Bm, bm, bn, K, 0);
    load_stage(sbase, 1, tid, A, Bm, bm, bn, K, BK_);
    load_stage(sbase, 2, tid, A, Bm, bm, bn, K, 2 * BK_);

    const int a_row = lane & 15;
    const int a_k16 = (lane >> 4) * 16;
    const int b_row = (lane & 7) + ((lane >> 4) << 3);
    const int b_k16 = ((lane >> 3) & 1) * 16;

    Frag f0, f1;

    // wait stage 0, preload fragments ks=0
    CP_WAIT(2);
    __syncthreads();
    load_frags(f0, sbase, 0, wm, wn, a_row, a_k16, b_row, b_k16);

    for (int i = 0; i < NITER; i++) {
        uint32_t st = sbase + (uint32_t)(i & 3) * STAGEB;

        // prefetch fragments for ks=1 of this stage, then MMA ks=0
        load_frags(f1, st, 32, wm, wn, a_row, a_k16, b_row, b_k16);
        run_mmas(acc, f0);

        // issue global loads for stage i+3
        if (i + 3 < NITER)
            load_stage(sbase, (i + 3) & 3, tid, A, Bm, bm, bn, K, (i + 3) * BK_);

        // make stage i+1 visible, prefetch its ks=0 fragments
        if (i + 1 < NITER) {
            if (i + 4 <= NITER)      CP_WAIT(2);
            else if (i + 3 == NITER) CP_WAIT(1);
            else                     CP_WAIT(0);
            __syncthreads();
            uint32_t stn = sbase + (uint32_t)((i + 1) & 3) * STAGEB;
            load_frags(f0, stn, 0, wm, wn, a_row, a_k16, b_row, b_k16);
        }

        // MMA ks=1 (overlaps with the f0 ldmatrix latency above)
        run_mmas(acc, f1);
    }

    // ---- epilogue (register -> global) ----
    const int rr = lane >> 2;
    const int cc = (lane & 3) * 2;
#pragma unroll
    for (int mf = 0; mf < 4; mf++) {
#pragma unroll
        for (int nf = 0; nf < 4; nf++) {
            const int row = bm + wm + mf * 16 + rr;
            const int col = bn + wn + nf * 8 + cc;
            float* a4 = acc[mf][nf];
            if (EPI == 0) {
                float* dst = Cf + (long long)bz * sC;
                *(float2*)&dst[(size_t)row * N + col]       = make_float2(a4[0], a4[1]);
                *(float2*)&dst[(size_t)(row + 8) * N + col] = make_float2(a4[2], a4[3]);
            } else {
                float b0 = bias[col], b1 = bias[col + 1];
                __half2 p0; p0.x = __float2half_rn(a4[0] + b0); p0.y = __float2half_rn(a4[1] + b1);
                __half2 p1; p1.x = __float2half_rn(a4[2] + b0); p1.y = __float2half_rn(a4[3] + b1);
                *(__half2*)&Ch[(size_t)row * N + col]       = p0;
                *(__half2*)&Ch[(size_t)(row + 8) * N + col] = p1;
            }
        }
    }
}

// ---------------------------------------------------------------------------
// Prep: round three fp32 tensors -> fp16 (one launch for X's, one for W's)
// ---------------------------------------------------------------------------
__global__ __launch_bounds__(256)
void round3_kernel(const float4* __restrict__ a, const float4* __restrict__ b,
                   const float4* __restrict__ c,
                   uint2* __restrict__ oa, uint2* __restrict__ ob,
                   uint2* __restrict__ oc, int blk_per)
{
    int bb = blockIdx.x;
    const float4* src; uint2* dst;
    if (bb < blk_per)            { src = a; dst = oa; }
    else if (bb < 2 * blk_per)   { src = b; dst = ob; bb -= blk_per; }
    else                         { src = c; dst = oc; bb -= 2 * blk_per; }
    int i = bb * 256 + threadIdx.x;
    float4 x = src[i];
    __align__(8) fp16 h[4];
    h[0] = __float2half_rn(x.x); h[1] = __float2half_rn(x.y);
    h[2] = __float2half_rn(x.z); h[3] = __float2half_rn(x.w);
    dst[i] = *(uint2*)h;
}
#define XBLK (B_ * S_ * D_ / 4 / 256)      // 16384
#define WBLK (D_ * D_ / 4 / 256)           // 1024

// ---------------------------------------------------------------------------
// per-batch transpose of V: [B][S][D] -> [B][D][S]
// ---------------------------------------------------------------------------
__global__ __launch_bounds__(256)
void transpose_kernel(const fp16* __restrict__ src, fp16* __restrict__ dst)
{
    __shared__ fp16 t[32][33];
    const int b = blockIdx.z;
    const int x0 = blockIdx.x * 32;   // D dim
    const int y0 = blockIdx.y * 32;   // S dim
    const int tx = threadIdx.x & 31;
    const int ty = threadIdx.x >> 5;  // 0..7
    const fp16* s = src + (size_t)b * S_ * D_;
    fp16* d = dst + (size_t)b * S_ * D_;
#pragma unroll
    for (int j = 0; j < 4; j++) {
        int r = ty + j * 8;
        t[r][tx] = s[(size_t)(y0 + r) * D_ + x0 + tx];
    }
    __syncthreads();
#pragma unroll
    for (int j = 0; j < 4; j++) {
        int r = ty + j * 8;
        d[(size_t)(x0 + r) * S_ + y0 + tx] = t[tx][r];
    }
}

// ---------------------------------------------------------------------------
// Masked softmax: fp32 raw scores (unscaled) -> fp16 prob row; applies 1/32.
// ---------------------------------------------------------------------------
__global__ __launch_bounds__(256)
void softmax_kernel(const float* __restrict__ scores, const int* __restrict__ mask,
                    fp16* __restrict__ P)
{
    const int row = blockIdx.x;               // 0..B*S-1
    const int b   = row / S_;
    const float* p = scores + (long long)row * S_;
    const int* mrow = mask + (long long)b * S_;

    const int tid = threadIdx.x;
    const int c0 = tid * 8;
    const float sc = 1.0f / 32.0f;            // 1/sqrt(1024)

    float4 v0 = *(const float4*)&p[c0];
    float4 v1 = *(const float4*)&p[c0 + 4];
    int4 m0 = *(const int4*)&mrow[c0];
    int4 m1 = *(const int4*)&mrow[c0 + 4];

    float v[8]  = {v0.x * sc, v0.y * sc, v0.z * sc, v0.w * sc,
                   v1.x * sc, v1.y * sc, v1.z * sc, v1.w * sc};
    int   mk[8] = {m0.x, m0.y, m0.z, m0.w, m1.x, m1.y, m1.z, m1.w};

    float mx = -CUDART_INF_F;
#pragma unroll
    for (int i = 0; i < 8; i++)
        if (mk[i]) mx = fmaxf(mx, v[i]);
#pragma unroll
    for (int o = 16; o > 0; o >>= 1)
        mx = fmaxf(mx, __shfl_xor_sync(0xFFFFFFFFu, mx, o));

    __shared__ float sred[8];
    if ((tid & 31) == 0) sred[tid >> 5] = mx;
    __syncthreads();
    mx = sred[0];
#pragma unroll
    for (int w = 1; w < 8; w++) mx = fmaxf(mx, sred[w]);
    __syncthreads();

    const float mxs = (mx > -CUDART_INF_F) ? mx : 0.f;

    float sum = 0.f;
#pragma unroll
    for (int i = 0; i < 8; i++) {
        float e = mk[i] ? __expf(v[i] - mxs) : 0.f;
        v[i] = e;
        sum += e;
    }
#pragma unroll
    for (int o = 16; o > 0; o >>= 1)
        sum += __shfl_xor_sync(0xFFFFFFFFu, sum, o);
    if ((tid & 31) == 0) sred[tid >> 5] = sum;
    __syncthreads();
    sum = 0.f;
#pragma unroll
    for (int w = 0; w < 8; w++) sum += sred[w];

    const float inv = (sum > 0.f) ? (1.f / sum) : 0.f;

    __align__(16) fp16 hh[8];
#pragma unroll
    for (int i = 0; i < 8; i++)
        hh[i] = __float2half_rn(v[i] * inv);
    *(uint4*)&P[(long long)row * S_ + c0] = *(uint4*)hh;
}

// ---------------------------------------------------------------------------
// Launch
// ---------------------------------------------------------------------------
extern "C" void kernel_launch(void* const* d_in, const int* in_sizes, int n_in,
                              void* d_out, int out_size)
{
    const float* query = (const float*)d_in[0];
    const float* key   = (const float*)d_in[1];
    const float* value = (const float*)d_in[2];
    const int*   mask  = (const int*)  d_in[3];
    const float* Wq    = (const float*)d_in[4];
    const float* bq    = (const float*)d_in[5];
    const float* Wk    = (const float*)d_in[6];
    const float* bk    = (const float*)d_in[7];
    const float* Wv    = (const float*)d_in[8];
    const float* bv    = (const float*)d_in[9];
    float* out = (float*)d_out;

    fp16 *Xq, *Xk, *Xv, *Wqh, *Wkh, *Wvh;
    fp16 *Q, *K, *V, *Vt, *P;
    float* Sc;
    cudaGetSymbolAddress((void**)&Xq,  gXq);
    cudaGetSymbolAddress((void**)&Xk,  gXk);
    cudaGetSymbolAddress((void**)&Xv,  gXv);
    cudaGetSymbolAddress((void**)&Wqh, gWq);
    cudaGetSymbolAddress((void**)&Wkh, gWk);
    cudaGetSymbolAddress((void**)&Wvh, gWv);
    cudaGetSymbolAddress((void**)&Q,   gQ);
    cudaGetSymbolAddress((void**)&K,   gK);
    cudaGetSymbolAddress((void**)&V,   gV);
    cudaGetSymbolAddress((void**)&Vt,  gVt);
    cudaGetSymbolAddress((void**)&P,   gP);
    cudaGetSymbolAddress((void**)&Sc,  gScores);

    cudaFuncSetAttribute(mma_gemm<0>, cudaFuncAttributeMaxDynamicSharedMemorySize, SMEM_DYN);
    cudaFuncSetAttribute(mma_gemm<1>, cudaFuncAttributeMaxDynamicSharedMemorySize, SMEM_DYN);

    const int M = B_ * S_;                  // 16384

    // launch 0: round X inputs to fp16
    round3_kernel<<<3 * XBLK, 256>>>((const float4*)query, (const float4*)key,
                                     (const float4*)value,
                                     (uint2*)Xq, (uint2*)Xk, (uint2*)Xv, XBLK);
    // launch 1: round weights to fp16
    round3_kernel<<<3 * WBLK, 256>>>((const float4*)Wq, (const float4*)Wk,
                                     (const float4*)Wv,
                                     (uint2*)Wqh, (uint2*)Wkh, (uint2*)Wvh, WBLK);

    // launches 2-4: projections (fp16 out, bias in epilogue)
    {
        dim3 g(D_ / 128, M / 128, 1);       // (8, 128)
        mma_gemm<1><<<g, 256, SMEM_DYN>>>(Xq, Wqh, bq, nullptr, Q, M, D_, D_, 0, 0, 0);
        mma_gemm<1><<<g, 256, SMEM_DYN>>>(Xk, Wkh, bk, nullptr, K, M, D_, D_, 0, 0, 0);
        mma_gemm<1><<<g, 256, SMEM_DYN>>>(Xv, Wvh, bv, nullptr, V, M, D_, D_, 0, 0, 0);
    }

    // launch 5 (ncu profiles this): scores = Q K^T per batch, fp32 out
    {
        dim3 g(S_ / 128, S_ / 128, B_);     // (16, 16, 8)
        mma_gemm<0><<<g, 256, SMEM_DYN>>>(Q, K, nullptr, Sc, nullptr, S_, S_, D_,
                                          (long long)S_ * D_, (long long)S_ * D_,
                                          (long long)S_ * S_);
    }

    // launch 6: transpose V per batch: [S,D] -> [D,S]
    {
        dim3 g(D_ / 32, S_ / 32, B_);
        transpose_kernel<<<g, 256>>>(V, Vt);
    }

    // launch 7: masked softmax (applies 1/sqrt(D)) -> fp16 P
    softmax_kernel<<<B_ * S_, 256>>>(Sc, mask, P);

    // launch 8: out = P V per batch (NT with V^T)
    {
        dim3 g(D_ / 128, S_ / 128, B_);     // (8, 16, 8)
        mma_gemm<0><<<g, 256, SMEM_DYN>>>(P, Vt, nullptr, out, nullptr, S_, D_, S_,
                                          (long long)S_ * S_, (long long)S_ * D_,
                                          (long long)S_ * D_);
    }
}

// round 12
// speedup vs baseline: 7.2969x; 1.1250x over previous
#include <cuda_runtime.h>
#include <cuda_fp16.h>
#include <math_constants.h>
#include <cstdint>

// ---------------------------------------------------------------------------
// Problem constants
// ---------------------------------------------------------------------------
#define B_ 8
#define S_ 2048
#define D_ 1024

typedef __half fp16;

// ---------------------------------------------------------------------------
// Scratch (device globals; allocation-free rule)
// ---------------------------------------------------------------------------
__device__ fp16 gXq[B_*S_*D_], gXk[B_*S_*D_], gXv[B_*S_*D_];
__device__ fp16 gWq[D_*D_], gWk[D_*D_], gWv[D_*D_];
__device__ fp16 gQ[B_*S_*D_], gK[B_*S_*D_], gV[B_*S_*D_];
__device__ fp16 gVt[B_*S_*D_];                // [B][D][S]
__device__ float gScores[B_*S_*S_];
__device__ fp16 gP[(long long)B_*S_*S_];

// ---------------------------------------------------------------------------
// PTX helpers (sm_80-baseline: cp.async, ldmatrix, mma.sync)
// ---------------------------------------------------------------------------
__device__ __forceinline__ uint32_t smem_u32(const void* p) {
    uint32_t a;
    asm("{ .reg .u64 t; cvta.to.shared.u64 t, %1; cvt.u32.u64 %0, t; }" : "=r"(a) : "l"(p));
    return a;
}
__device__ __forceinline__ void cp16(uint32_t dst, const void* src) {
    asm volatile("cp.async.cg.shared.global [%0], [%1], 16;"
                 :: "r"(dst), "l"(__cvta_generic_to_global(src)) : "memory");
}
#define CP_COMMIT() asm volatile("cp.async.commit_group;" ::: "memory")
#define CP_WAIT(n)  asm volatile("cp.async.wait_group %0;" :: "n"(n) : "memory")

__device__ __forceinline__ void ldm_x4(uint32_t* r, uint32_t addr) {
    asm volatile("ldmatrix.sync.aligned.m8n8.x4.shared.b16 {%0,%1,%2,%3}, [%4];"
                 : "=r"(r[0]), "=r"(r[1]), "=r"(r[2]), "=r"(r[3]) : "r"(addr));
}
__device__ __forceinline__ void mma_fp16(float* d, const uint32_t* a, const uint32_t* b) {
    asm volatile("mma.sync.aligned.m16n8k16.row.col.f32.f16.f16.f32 "
                 "{%0,%1,%2,%3}, {%4,%5,%6,%7}, {%8,%9}, {%0,%1,%2,%3};"
                 : "+f"(d[0]), "+f"(d[1]), "+f"(d[2]), "+f"(d[3])
                 : "r"(a[0]), "r"(a[1]), "r"(a[2]), "r"(a[3]), "r"(b[0]), "r"(b[1]));
}

// ---------------------------------------------------------------------------
// GEMM: C[M,N] = A[M,K] * B[N,K]^T, single-pass fp16, mma.sync
// Tile 128x128, BK=32, 4 warps (2m x 2n, each 64x64), 4-stage cp.async,
// register-level fragment double buffering.
// SMEM rows: 32 fp16 = 64B at 80B stride (conflict-free ldmatrix).
// EPI==0: fp32 store of acc. EPI==1: fp16 store of acc+bias.
// ---------------------------------------------------------------------------
#define BK_ 32
#define ROWB 80
#define MATB (128 * ROWB)          // 10240
#define STAGEB (2 * MATB)          // 20480 (A, B)
#define NSTAGE 4
#define SMEM_DYN (NSTAGE * STAGEB) // 81920 -> 2 CTAs/SM
#define NTHREADS 128

struct Frag {
    uint32_t a[4][4];
    uint32_t b[8][2];
};

__device__ __forceinline__ void load_stage(uint32_t sbase, int slot, int tid,
                                           const fp16* A, const fp16* Bm,
                                           int bm, int bn, int K, int k0)
{
    uint32_t sb = sbase + (uint32_t)slot * STAGEB;
#pragma unroll
    for (int t = 0; t < 4; t++) {
        int u = tid + NTHREADS * t;         // 0..511
        int row = u >> 2;                   // 0..127
        int c = (u & 3) * 16;               // byte offset within 64B row
        uint32_t so = (uint32_t)(row * ROWB + c);
        size_t gA = (size_t)(bm + row) * K + k0 + (c >> 1);
        size_t gB = (size_t)(bn + row) * K + k0 + (c >> 1);
        cp16(sb + so,        A  + gA);
        cp16(sb + MATB + so, Bm + gB);
    }
    CP_COMMIT();
}

__device__ __forceinline__ void load_frags(Frag& f, uint32_t st, int kb,
                                           int wm, int wn,
                                           int a_row, int a_k16,
                                           int b_row, int b_k16)
{
#pragma unroll
    for (int mf = 0; mf < 4; mf++) {
        uint32_t ra = st + (uint32_t)((wm + mf * 16 + a_row) * ROWB + kb + a_k16);
        ldm_x4(f.a[mf], ra);
    }
#pragma unroll
    for (int np = 0; np < 4; np++) {
        uint32_t rb = st + MATB +
                      (uint32_t)((wn + np * 16 + b_row) * ROWB + kb + b_k16);
        uint32_t th[4];
        ldm_x4(th, rb);
        f.b[np*2][0]   = th[0]; f.b[np*2][1]   = th[1];
        f.b[np*2+1][0] = th[2]; f.b[np*2+1][1] = th[3];
    }
}

__device__ __forceinline__ void run_mmas(float acc[4][8][4], const Frag& f)
{
#pragma unroll
    for (int mf = 0; mf < 4; mf++)
#pragma unroll
        for (int nf = 0; nf < 8; nf++)
            mma_fp16(acc[mf][nf], f.a[mf], f.b[nf]);
}

template <int EPI>
__global__ __launch_bounds__(NTHREADS, 2)
void mma_gemm(const fp16* __restrict__ A, const fp16* __restrict__ Bm,
              const float* __restrict__ bias,
              float* __restrict__ Cf, fp16* __restrict__ Ch,
              int M, int N, int K,
              long long sA, long long sB, long long sC)
{
    extern __shared__ char smem[];
    const int tid  = threadIdx.x;
    const int wid  = tid >> 5;              // 0..3
    const int lane = tid & 31;

    const int bz = blockIdx.z;
    A  += (long long)bz * sA;
    Bm += (long long)bz * sB;

    const int bm = blockIdx.y * 128;
    const int bn = blockIdx.x * 128;
    const int wm = (wid >> 1) * 64;
    const int wn = (wid & 1) * 64;

    const uint32_t sbase = smem_u32(smem);

    float acc[4][8][4];
#pragma unroll
    for (int i = 0; i < 4; i++)
#pragma unroll
        for (int j = 0; j < 8; j++)
#pragma unroll
            for (int q = 0; q < 4; q++) acc[i][j][q] = 0.f;

    const int NITER = K / BK_;

    load_stage(sbase, 0, tid, A, Bm, bm, bn, K, 0);
    load_stage(sbase, 1, tid, A, Bm, bm, bn, K, BK_);
    load_stage(sbase, 2, tid, A, Bm, bm, bn, K, 2 * BK_);

    const int a_row = lane & 15;
    const int a_k16 = (lane >> 4) * 16;
    const int b_row = (lane & 7) + ((lane >> 4) << 3);
    const int b_k16 = ((lane >> 3) & 1) * 16;

    Frag f0, f1;

    // wait stage 0, preload fragments ks=0
    CP_WAIT(2);
    __syncthreads();
    load_frags(f0, sbase, 0, wm, wn, a_row, a_k16, b_row, b_k16);

    for (int i = 0; i < NITER; i++) {
        uint32_t st = sbase + (uint32_t)(i & 3) * STAGEB;

        // prefetch fragments for ks=1 of this stage, then MMA ks=0
        load_frags(f1, st, 32, wm, wn, a_row, a_k16, b_row, b_k16);
        run_mmas(acc, f0);

        // issue global loads for stage i+3
        if (i + 3 < NITER)
            load_stage(sbase, (i + 3) & 3, tid, A, Bm, bm, bn, K, (i + 3) * BK_);

        // make stage i+1 visible, prefetch its ks=0 fragments
        if (i + 1 < NITER) {
            if (i + 4 <= NITER)      CP_WAIT(2);
            else if (i + 3 == NITER) CP_WAIT(1);
            else                     CP_WAIT(0);
            __syncthreads();
            uint32_t stn = sbase + (uint32_t)((i + 1) & 3) * STAGEB;
            load_frags(f0, stn, 0, wm, wn, a_row, a_k16, b_row, b_k16);
        }

        // MMA ks=1 (overlaps with the f0 ldmatrix latency above)
        run_mmas(acc, f1);
    }

    // ---- epilogue (register -> global) ----
    const int rr = lane >> 2;
    const int cc = (lane & 3) * 2;
#pragma unroll
    for (int mf = 0; mf < 4; mf++) {
#pragma unroll
        for (int nf = 0; nf < 8; nf++) {
            const int row = bm + wm + mf * 16 + rr;
            const int col = bn + wn + nf * 8 + cc;
            float* a4 = acc[mf][nf];
            if (EPI == 0) {
                float* dst = Cf + (long long)bz * sC;
                *(float2*)&dst[(size_t)row * N + col]       = make_float2(a4[0], a4[1]);
                *(float2*)&dst[(size_t)(row + 8) * N + col] = make_float2(a4[2], a4[3]);
            } else {
                float b0 = bias[col], b1 = bias[col + 1];
                __half2 p0; p0.x = __float2half_rn(a4[0] + b0); p0.y = __float2half_rn(a4[1] + b1);
                __half2 p1; p1.x = __float2half_rn(a4[2] + b0); p1.y = __float2half_rn(a4[3] + b1);
                *(__half2*)&Ch[(size_t)row * N + col]       = p0;
                *(__half2*)&Ch[(size_t)(row + 8) * N + col] = p1;
            }
        }
    }
}

// ---------------------------------------------------------------------------
// Prep: round three fp32 tensors -> fp16 (one launch for X's, one for W's)
// ---------------------------------------------------------------------------
__global__ __launch_bounds__(256)
void round3_kernel(const float4* __restrict__ a, const float4* __restrict__ b,
                   const float4* __restrict__ c,
                   uint2* __restrict__ oa, uint2* __restrict__ ob,
                   uint2* __restrict__ oc, int blk_per)
{
    int bb = blockIdx.x;
    const float4* src; uint2* dst;
    if (bb < blk_per)            { src = a; dst = oa; }
    else if (bb < 2 * blk_per)   { src = b; dst = ob; bb -= blk_per; }
    else                         { src = c; dst = oc; bb -= 2 * blk_per; }
    int i = bb * 256 + threadIdx.x;
    float4 x = src[i];
    __align__(8) fp16 h[4];
    h[0] = __float2half_rn(x.x); h[1] = __float2half_rn(x.y);
    h[2] = __float2half_rn(x.z); h[3] = __float2half_rn(x.w);
    dst[i] = *(uint2*)h;
}
#define XBLK (B_ * S_ * D_ / 4 / 256)      // 16384
#define WBLK (D_ * D_ / 4 / 256)           // 1024

// ---------------------------------------------------------------------------
// per-batch transpose of V: [B][S][D] -> [B][D][S]
// ---------------------------------------------------------------------------
__global__ __launch_bounds__(256)
void transpose_kernel(const fp16* __restrict__ src, fp16* __restrict__ dst)
{
    __shared__ fp16 t[32][33];
    const int b = blockIdx.z;
    const int x0 = blockIdx.x * 32;   // D dim
    const int y0 = blockIdx.y * 32;   // S dim
    const int tx = threadIdx.x & 31;
    const int ty = threadIdx.x >> 5;  // 0..7
    const fp16* s = src + (size_t)b * S_ * D_;
    fp16* d = dst + (size_t)b * S_ * D_;
#pragma unroll
    for (int j = 0; j < 4; j++) {
        int r = ty + j * 8;
        t[r][tx] = s[(size_t)(y0 + r) * D_ + x0 + tx];
    }
    __syncthreads();
#pragma unroll
    for (int j = 0; j < 4; j++) {
        int r = ty + j * 8;
        d[(size_t)(x0 + r) * S_ + y0 + tx] = t[tx][r];
    }
}

// ---------------------------------------------------------------------------
// Masked softmax: fp32 raw scores (unscaled) -> fp16 prob row; applies 1/32.
// ---------------------------------------------------------------------------
__global__ __launch_bounds__(256)
void softmax_kernel(const float* __restrict__ scores, const int* __restrict__ mask,
                    fp16* __restrict__ P)
{
    const int row = blockIdx.x;               // 0..B*S-1
    const int b   = row / S_;
    const float* p = scores + (long long)row * S_;
    const int* mrow = mask + (long long)b * S_;

    const int tid = threadIdx.x;
    const int c0 = tid * 8;
    const float sc = 1.0f / 32.0f;            // 1/sqrt(1024)

    float4 v0 = *(const float4*)&p[c0];
    float4 v1 = *(const float4*)&p[c0 + 4];
    int4 m0 = *(const int4*)&mrow[c0];
    int4 m1 = *(const int4*)&mrow[c0 + 4];

    float v[8]  = {v0.x * sc, v0.y * sc, v0.z * sc, v0.w * sc,
                   v1.x * sc, v1.y * sc, v1.z * sc, v1.w * sc};
    int   mk[8] = {m0.x, m0.y, m0.z, m0.w, m1.x, m1.y, m1.z, m1.w};

    float mx = -CUDART_INF_F;
#pragma unroll
    for (int i = 0; i < 8; i++)
        if (mk[i]) mx = fmaxf(mx, v[i]);
#pragma unroll
    for (int o = 16; o > 0; o >>= 1)
        mx = fmaxf(mx, __shfl_xor_sync(0xFFFFFFFFu, mx, o));

    __shared__ float sred[8];
    if ((tid & 31) == 0) sred[tid >> 5] = mx;
    __syncthreads();
    mx = sred[0];
#pragma unroll
    for (int w = 1; w < 8; w++) mx = fmaxf(mx, sred[w]);
    __syncthreads();

    const float mxs = (mx > -CUDART_INF_F) ? mx : 0.f;

    float sum = 0.f;
#pragma unroll
    for (int i = 0; i < 8; i++) {
        float e = mk[i] ? __expf(v[i] - mxs) : 0.f;
        v[i] = e;
        sum += e;
    }
#pragma unroll
    for (int o = 16; o > 0; o >>= 1)
        sum += __shfl_xor_sync(0xFFFFFFFFu, sum, o);
    if ((tid & 31) == 0) sred[tid >> 5] = sum;
    __syncthreads();
    sum = 0.f;
#pragma unroll
    for (int w = 0; w < 8; w++) sum += sred[w];

    const float inv = (sum > 0.f) ? (1.f / sum) : 0.f;

    __align__(16) fp16 hh[8];
#pragma unroll
    for (int i = 0; i < 8; i++)
        hh[i] = __float2half_rn(v[i] * inv);
    *(uint4*)&P[(long long)row * S_ + c0] = *(uint4*)hh;
}

// ---------------------------------------------------------------------------
// Launch
// ---------------------------------------------------------------------------
extern "C" void kernel_launch(void* const* d_in, const int* in_sizes, int n_in,
                              void* d_out, int out_size)
{
    const float* query = (const float*)d_in[0];
    const float* key   = (const float*)d_in[1];
    const float* value = (const float*)d_in[2];
    const int*   mask  = (const int*)  d_in[3];
    const float* Wq    = (const float*)d_in[4];
    const float* bq    = (const float*)d_in[5];
    const float* Wk    = (const float*)d_in[6];
    const float* bk    = (const float*)d_in[7];
    const float* Wv    = (const float*)d_in[8];
    const float* bv    = (const float*)d_in[9];
    float* out = (float*)d_out;

    fp16 *Xq, *Xk, *Xv, *Wqh, *Wkh, *Wvh;
    fp16 *Q, *K, *V, *Vt, *P;
    float* Sc;
    cudaGetSymbolAddress((void**)&Xq,  gXq);
    cudaGetSymbolAddress((void**)&Xk,  gXk);
    cudaGetSymbolAddress((void**)&Xv,  gXv);
    cudaGetSymbolAddress((void**)&Wqh, gWq);
    cudaGetSymbolAddress((void**)&Wkh, gWk);
    cudaGetSymbolAddress((void**)&Wvh, gWv);
    cudaGetSymbolAddress((void**)&Q,   gQ);
    cudaGetSymbolAddress((void**)&K,   gK);
    cudaGetSymbolAddress((void**)&V,   gV);
    cudaGetSymbolAddress((void**)&Vt,  gVt);
    cudaGetSymbolAddress((void**)&P,   gP);
    cudaGetSymbolAddress((void**)&Sc,  gScores);

    cudaFuncSetAttribute(mma_gemm<0>, cudaFuncAttributeMaxDynamicSharedMemorySize, SMEM_DYN);
    cudaFuncSetAttribute(mma_gemm<1>, cudaFuncAttributeMaxDynamicSharedMemorySize, SMEM_DYN);

    const int M = B_ * S_;                  // 16384

    // launch 0: round X inputs to fp16
    round3_kernel<<<3 * XBLK, 256>>>((const float4*)query, (const float4*)key,
                                     (const float4*)value,
                                     (uint2*)Xq, (uint2*)Xk, (uint2*)Xv, XBLK);
    // launch 1: round weights to fp16
    round3_kernel<<<3 * WBLK, 256>>>((const float4*)Wq, (const float4*)Wk,
                                     (const float4*)Wv,
                                     (uint2*)Wqh, (uint2*)Wkh, (uint2*)Wvh, WBLK);

    // launches 2-4: projections (fp16 out, bias in epilogue)
    {
        dim3 g(D_ / 128, M / 128, 1);       // (8, 128)
        mma_gemm<1><<<g, NTHREADS, SMEM_DYN>>>(Xq, Wqh, bq, nullptr, Q, M, D_, D_, 0, 0, 0);
        mma_gemm<1><<<g, NTHREADS, SMEM_DYN>>>(Xk, Wkh, bk, nullptr, K, M, D_, D_, 0, 0, 0);
        mma_gemm<1><<<g, NTHREADS, SMEM_DYN>>>(Xv, Wvh, bv, nullptr, V, M, D_, D_, 0, 0, 0);
    }

    // launch 5 (ncu profiles this): scores = Q K^T per batch, fp32 out
    {
        dim3 g(S_ / 128, S_ / 128, B_);     // (16, 16, 8)
        mma_gemm<0><<<g, NTHREADS, SMEM_DYN>>>(Q, K, nullptr, Sc, nullptr, S_, S_, D_,
                                               (long long)S_ * D_, (long long)S_ * D_,
                                               (long long)S_ * S_);
    }

    // launch 6: transpose V per batch: [S,D] -> [D,S]
    {
        dim3 g(D_ / 32, S_ / 32, B_);
        transpose_kernel<<<g, 256>>>(V, Vt);
    }

    // launch 7: masked softmax (applies 1/sqrt(D)) -> fp16 P
    softmax_kernel<<<B_ * S_, 256>>>(Sc, mask, P);

    // launch 8: out = P V per batch (NT with V^T)
    {
        dim3 g(D_ / 128, S_ / 128, B_);     // (8, 16, 8)
        mma_gemm<0><<<g, NTHREADS, SMEM_DYN>>>(P, Vt, nullptr, out, nullptr, S_, D_, S_,
                                               (long long)S_ * S_, (long long)S_ * D_,
                                               (long long)S_ * D_);
    }
}